// round 12
// baseline (speedup 1.0000x reference)
#include <cuda_runtime.h>
#include <math.h>

#define Nn 50000
#define Ee 800000
#define Cc 100000
#define D 128
#define NEG 0.01f
#define BN_EPS 1e-5f
#define NB_SCAN 49

#define FMA2(d, a, b) asm("fma.rn.f32x2 %0, %1, %2, %0;" : "+l"(d) : "l"(a), "l"(b))
#define UNPACK2(lo, hi, v) asm("mov.b64 {%0, %1}, %2;" : "=f"(lo), "=f"(hi) : "l"(v))

// ---------------- scratch (static __device__, no allocation) ----------------
__device__ float g_h0[(size_t)Nn * D];
__device__ float g_h1[(size_t)Nn * D];
__device__ float g_agg[(size_t)Nn * D];
__device__ float g_pu[(size_t)Nn * 64];
__device__ float g_pv[(size_t)Nn * 64];
__device__ int   g_deg[Nn];
__device__ int   g_off[Nn + 1];
__device__ int   g_cur[Nn];
__device__ int   g_csr[Ee];
__device__ unsigned long long g_lb[NB_SCAN];  // lookback: (aggregate<<1)|1
__device__ unsigned int g_done;
__device__ float g_part[256];

// ---------------- zero state ----------------
__global__ void k_zero() {
    int i = blockIdx.x * blockDim.x + threadIdx.x;
    if (i < Nn) g_deg[i] = 0;
    if (i < NB_SCAN) g_lb[i] = 0ull;
    if (i == 0) g_done = 0u;
}

__global__ void k_count(const int* __restrict__ dst, int E) {
    for (int e = blockIdx.x * blockDim.x + threadIdx.x; e < E; e += gridDim.x * blockDim.x)
        atomicAdd(&g_deg[dst[e]], 1);
}

// ---------------- single-pass: scan (lookback) + grid barrier + CSR fill ----------------
__global__ void k_scanfill(const int* __restrict__ src, const int* __restrict__ dst, int E) {
    __shared__ int ws[32];
    __shared__ int preds[64];
    __shared__ int sbase;
    int b = blockIdx.x;
    int tid = threadIdx.x;
    int i = b * 1024 + tid;
    int lane = tid & 31, wid = tid >> 5;
    int v = (i < Nn) ? g_deg[i] : 0;
    int s = v;
#pragma unroll
    for (int o = 1; o < 32; o <<= 1) {
        int t = __shfl_up_sync(0xffffffffu, s, o);
        if (lane >= o) s += t;
    }
    if (lane == 31) ws[wid] = s;
    __syncthreads();
    if (wid == 0) {
        int t = ws[lane];
#pragma unroll
        for (int o = 1; o < 32; o <<= 1) {
            int u = __shfl_up_sync(0xffffffffu, t, o);
            if (lane >= o) t += u;
        }
        ws[lane] = t;
    }
    __syncthreads();
    s += wid ? ws[wid - 1] : 0;  // local inclusive

    if (tid == 1023)
        atomicExch(&g_lb[b], (((unsigned long long)(unsigned)s) << 1) | 1ull);

    if (tid < b) {
        unsigned long long x;
        do { x = atomicAdd(&g_lb[tid], 0ull); } while (!(x & 1ull));
        preds[tid] = (int)(x >> 1);
    }
    __syncthreads();
    if (tid == 0) {
        int acc = 0;
        for (int j = 0; j < b; j++) acc += preds[j];
        sbase = acc;
    }
    __syncthreads();
    s += sbase;

    if (i < Nn) {
        g_off[i + 1] = s;
        g_cur[i] = s - v;
    }
    if (i == 0) g_off[0] = 0;

    __threadfence();
    __syncthreads();
    if (tid == 0) {
        atomicAdd(&g_done, 1u);
        while (atomicAdd(&g_done, 0u) < (unsigned)gridDim.x) {}
    }
    __syncthreads();

    int stride = gridDim.x * 1024;
    for (int e = b * 1024 + tid; e < E; e += stride) {
        int d = dst[e];
        int p = atomicAdd(&g_cur[d], 1);
        g_csr[p] = src[e];
    }
}

// ---------------- segment-mean aggregation (warp per node, no smem, high occ) ----------------
__global__ void k_agg(const float* __restrict__ A, float* __restrict__ out) {
    int w = threadIdx.x >> 5, l = threadIdx.x & 31;
    int node = blockIdx.x * 8 + w;
    if (node >= Nn) return;
    int s = g_off[node], e = g_off[node + 1];
    int deg = e - s;
    float4 a0 = make_float4(0.f, 0.f, 0.f, 0.f);
    float4 a1 = make_float4(0.f, 0.f, 0.f, 0.f);
    float4 a2 = make_float4(0.f, 0.f, 0.f, 0.f);
    float4 a3 = make_float4(0.f, 0.f, 0.f, 0.f);
    for (int base = s; base < e; base += 32) {
        int cnt = e - base; if (cnt > 32) cnt = 32;
        int idx = (l < cnt) ? g_csr[base + l] : 0;
        int j = 0;
        for (; j + 4 <= cnt; j += 4) {
            int r0 = __shfl_sync(0xffffffffu, idx, j);
            int r1 = __shfl_sync(0xffffffffu, idx, j + 1);
            int r2 = __shfl_sync(0xffffffffu, idx, j + 2);
            int r3 = __shfl_sync(0xffffffffu, idx, j + 3);
            float4 v0 = ((const float4*)(A + (size_t)r0 * D))[l];
            float4 v1 = ((const float4*)(A + (size_t)r1 * D))[l];
            float4 v2 = ((const float4*)(A + (size_t)r2 * D))[l];
            float4 v3 = ((const float4*)(A + (size_t)r3 * D))[l];
            a0.x += v0.x; a0.y += v0.y; a0.z += v0.z; a0.w += v0.w;
            a1.x += v1.x; a1.y += v1.y; a1.z += v1.z; a1.w += v1.w;
            a2.x += v2.x; a2.y += v2.y; a2.z += v2.z; a2.w += v2.w;
            a3.x += v3.x; a3.y += v3.y; a3.z += v3.z; a3.w += v3.w;
        }
        for (; j < cnt; j++) {
            int r = __shfl_sync(0xffffffffu, idx, j);
            float4 vv = ((const float4*)(A + (size_t)r * D))[l];
            a0.x += vv.x; a0.y += vv.y; a0.z += vv.z; a0.w += vv.w;
        }
    }
    a0.x += a1.x + a2.x + a3.x;
    a0.y += a1.y + a2.y + a3.y;
    a0.z += a1.z + a2.z + a3.z;
    a0.w += a1.w + a2.w + a3.w;
    float inv = 1.0f / (float)(deg > 1 ? deg : 1);
    a0.x *= inv; a0.y *= inv; a0.z *= inv; a0.w *= inv;
    ((float4*)(out + (size_t)node * D))[l] = a0;
}

// ---------------- dual GEMM + BN + leaky (k-pair f32x2, pair-packed values) ----------------
// 64 nodes/block, 512 threads. Warp w: node group g=w>>1 (8 nodes), col half h=w&1 (64 cols).
// Thread: 8 nodes x cols {64h+2l, 64h+2l+1}.
// smem: sWsP[16384] (k-pair interleaved), sWnP[16384],
//       sVal[32 pairs x 512] (x pair-packed 256 + a pair-packed 256) -> 192KB
__global__ void k_gemm(const float* __restrict__ A, const float* __restrict__ G,
                       const float* __restrict__ Ws, const float* __restrict__ Wn,
                       const float* __restrict__ bias, const float* __restrict__ gamma,
                       const float* __restrict__ beta, const float* __restrict__ rm,
                       const float* __restrict__ rv, float* __restrict__ out, int fixnan) {
    extern __shared__ float sm[];
    float* sWsP = sm;               // [0, 16384)
    float* sWnP = sm + 16384;       // [16384, 32768)
    float* sVal = sm + 32768;       // [32768, 49152)  pair stride 512
    for (int idx = threadIdx.x; idx < 4096; idx += 512) {
        int kp = idx >> 6;
        int cg = idx & 63;
        float2 a0 = *(const float2*)&Ws[(2 * kp) * 128 + 2 * cg];
        float2 b0 = *(const float2*)&Ws[(2 * kp + 1) * 128 + 2 * cg];
        *(float4*)&sWsP[(kp * 128 + 2 * cg) * 2] = make_float4(a0.x, b0.x, a0.y, b0.y);
        float2 a1 = *(const float2*)&Wn[(2 * kp) * 128 + 2 * cg];
        float2 b1 = *(const float2*)&Wn[(2 * kp + 1) * 128 + 2 * cg];
        *(float4*)&sWnP[(kp * 128 + 2 * cg) * 2] = make_float4(a1.x, b1.x, a1.y, b1.y);
    }

    int w = threadIdx.x >> 5, l = threadIdx.x & 31;
    int blockBase = blockIdx.x * 64;

    // value staging: warp stages its 4 nodes as 2 pairs, pair-packed per k-pair:
    // x entry for pair p, kp: {nA.v2kp, nA.v2kp+1, nB.v2kp, nB.v2kp+1} at sVal[p*512 + kp*4]
    // a entries at +256.
#pragma unroll
    for (int pr = 0; pr < 2; pr++) {
        int p = w * 2 + pr;
        int nA = blockBase + p * 2, nB = nA + 1;
        float4 xA = make_float4(0.f, 0.f, 0.f, 0.f), xB = xA, aA = xA, aB = xA;
        if (nA < Nn) {
            xA = ((const float4*)(A + (size_t)nA * D))[l];
            aA = ((const float4*)(G + (size_t)nA * D))[l];
        }
        if (nB < Nn) {
            xB = ((const float4*)(A + (size_t)nB * D))[l];
            aB = ((const float4*)(G + (size_t)nB * D))[l];
        }
        float* bx = sVal + p * 512;
        // lane l holds k = 4l..4l+3 -> kp = 2l (k 4l,4l+1) and kp = 2l+1 (k 4l+2,4l+3)
        *(float4*)(bx + 8 * l)           = make_float4(xA.x, xA.y, xB.x, xB.y);
        *(float4*)(bx + 8 * l + 4)       = make_float4(xA.z, xA.w, xB.z, xB.w);
        *(float4*)(bx + 256 + 8 * l)     = make_float4(aA.x, aA.y, aB.x, aB.y);
        *(float4*)(bx + 256 + 8 * l + 4) = make_float4(aA.z, aA.w, aB.z, aB.w);
    }
    __syncthreads();

    // main loop
    int g = w >> 1, h = w & 1;
    const float* wsb = sWsP + 128 * h + 4 * l;
    const float* wnb = sWnP + 128 * h + 4 * l;
    const float* vb = sVal + g * 4 * 512;  // 4 pairs for this warp's 8 nodes
    unsigned long long acc[8][2];
#pragma unroll
    for (int n = 0; n < 8; n++) { acc[n][0] = 0ull; acc[n][1] = 0ull; }
#pragma unroll 4
    for (int kp = 0; kp < 64; kp++) {
        ulonglong2 wS = *(const ulonglong2*)(wsb + kp * 256);
        ulonglong2 wN = *(const ulonglong2*)(wnb + kp * 256);
#pragma unroll
        for (int p = 0; p < 4; p++) {
            ulonglong2 vx = *(const ulonglong2*)(vb + p * 512 + kp * 4);
            ulonglong2 va = *(const ulonglong2*)(vb + p * 512 + 256 + kp * 4);
            FMA2(acc[2 * p][0], vx.x, wS.x);     FMA2(acc[2 * p][1], vx.x, wS.y);
            FMA2(acc[2 * p + 1][0], vx.y, wS.x); FMA2(acc[2 * p + 1][1], vx.y, wS.y);
            FMA2(acc[2 * p][0], va.x, wN.x);     FMA2(acc[2 * p][1], va.x, wN.y);
            FMA2(acc[2 * p + 1][0], va.y, wN.x); FMA2(acc[2 * p + 1][1], va.y, wN.y);
        }
    }

    // epilogue: cols c0 = 64h + 2l, c1 = c0 + 1 for nodes blockBase + 8g + n
    int c0 = 64 * h + 2 * l;
    float2 bb = *(const float2*)&bias[c0];
    float2 ga = *(const float2*)&gamma[c0];
    float2 be = *(const float2*)&beta[c0];
    float2 rmv = *(const float2*)&rm[c0];
    float2 rvv = *(const float2*)&rv[c0];
    float scl0 = ga.x * rsqrtf(rvv.x + BN_EPS), shf0 = be.x - rmv.x * scl0;
    float scl1 = ga.y * rsqrtf(rvv.y + BN_EPS), shf1 = be.y - rmv.y * scl1;
#pragma unroll
    for (int n = 0; n < 8; n++) {
        int node = blockBase + 8 * g + n;
        if (node >= Nn) continue;
        float pe, po;
        UNPACK2(pe, po, acc[n][0]);
        float v0 = (pe + po) + bb.x;
        v0 = v0 * scl0 + shf0;
        v0 = v0 >= 0.f ? v0 : NEG * v0;
        UNPACK2(pe, po, acc[n][1]);
        float v1 = (pe + po) + bb.y;
        v1 = v1 * scl1 + shf1;
        v1 = v1 >= 0.f ? v1 : NEG * v1;
        if (fixnan) {
            if (isnan(v0)) v0 = 1e-14f;
            else if (isinf(v0)) v0 = v0 > 0.f ? 3.402823466e38f : -3.402823466e38f;
            if (isnan(v1)) v1 = 1e-14f;
            else if (isinf(v1)) v1 = v1 > 0.f ? 3.402823466e38f : -3.402823466e38f;
        }
        *(float2*)&out[(size_t)node * D + c0] = make_float2(v0, v1);
    }
}

// ---------------- node-level MLP layer0 projection (f32x2) ----------------
__global__ void k_prep(const float* __restrict__ h, const float* __restrict__ mw0,
                       float* __restrict__ pu, float* __restrict__ pv) {
    extern __shared__ float sm[];
    float* sWI = sm;            // [0, 16384)
    float* sVal = sm + 16384;   // [16384, 32768)  node stride 256
    for (int idx = threadIdx.x; idx < 4096; idx += 512) {
        int k = idx >> 5, p = idx & 31;
        float2 u = *(const float2*)&mw0[k * 64 + 2 * p];
        float2 v = *(const float2*)&mw0[(128 + k) * 64 + 2 * p];
        *(float4*)&sWI[k * 128 + p * 4] = make_float4(u.x, u.y, v.x, v.y);
    }
    __syncthreads();

    int w = threadIdx.x >> 5, l = threadIdx.x & 31;
    int nl0 = w * 4;
    int n0 = blockIdx.x * 64 + nl0;

#pragma unroll
    for (int t = 0; t < 4; t++) {
        int node = n0 + t;
        float4 xv = make_float4(0.f, 0.f, 0.f, 0.f);
        if (node < Nn) xv = ((const float4*)(h + (size_t)node * D))[l];
        float4* sd = (float4*)(sVal + (nl0 + t) * 256 + l * 8);
        sd[0] = make_float4(xv.x, xv.x, xv.y, xv.y);
        sd[1] = make_float4(xv.z, xv.z, xv.w, xv.w);
    }
    __syncwarp();

    unsigned long long au[4] = {0ull, 0ull, 0ull, 0ull};
    unsigned long long av[4] = {0ull, 0ull, 0ull, 0ull};
    const float* wib = sWI + l * 4;
    const float* vb = sVal + nl0 * 256;
#pragma unroll 8
    for (int k = 0; k < 128; k++) {
        ulonglong2 wp = *(const ulonglong2*)(wib + k * 128);
#pragma unroll
        for (int t = 0; t < 4; t++) {
            unsigned long long xd = *(const unsigned long long*)(vb + t * 256 + 2 * k);
            FMA2(au[t], xd, wp.x);
            FMA2(av[t], xd, wp.y);
        }
    }
#pragma unroll
    for (int t = 0; t < 4; t++) {
        int node = n0 + t;
        if (node >= Nn) continue;
        *(float2*)&pu[(size_t)node * 64 + 2 * l] = *(float2*)&au[t];
        *(float2*)&pv[(size_t)node * 64 + 2 * l] = *(float2*)&av[t];
    }
}

// ---------------- candidate kernel ----------------
#define Z0STRIDE 136
#define CAND_SMEM_FLOATS 13060
__global__ void k_cand(const float* __restrict__ pu, const float* __restrict__ pv,
                       const int* __restrict__ cu, const int* __restrict__ cv,
                       const float* __restrict__ cf,
                       const float* __restrict__ mw0, const float* __restrict__ mb0,
                       const float* __restrict__ mw1, const float* __restrict__ mb1,
                       const float* __restrict__ mw2, const float* __restrict__ mb2,
                       float* __restrict__ y, int C) {
    extern __shared__ float smc[];
    float* w1s = smc;
    float* z0sD = smc + 4096;
    float* wfs = smc + 12800;
    float* b0s = smc + 12864;
    float* b1s = smc + 12928;
    float* w2s = smc + 12992;
    float* b2s = smc + 13056;
    int tid = threadIdx.x;
    for (int i = tid; i < 4096; i += 256) w1s[i] = mw1[i];
    if (tid < 64) {
        wfs[tid] = mw0[256 * 64 + tid];
        b0s[tid] = mb0[tid];
        b1s[tid] = mb1[tid];
        w2s[tid] = mw2[tid];
    }
    if (tid == 0) b2s[0] = mb2[0];
    __syncthreads();

    int base = blockIdx.x * 64;

    {
        int jc = tid & 15, j = jc * 4;
        int c0 = tid >> 4;
#pragma unroll
        for (int i = 0; i < 4; i++) {
            int cl = c0 + 16 * i;
            int gc = base + cl;
            float4 z = make_float4(0.f, 0.f, 0.f, 0.f);
            if (gc < C) {
                int u = cu[gc], v = cv[gc];
                float f = cf[gc];
                float4 a = *(const float4*)&pu[(size_t)u * 64 + j];
                float4 b = *(const float4*)&pv[(size_t)v * 64 + j];
                float4 wf4 = *(const float4*)&wfs[j];
                float4 bb4 = *(const float4*)&b0s[j];
                z.x = a.x + b.x + f * wf4.x + bb4.x;
                z.y = a.y + b.y + f * wf4.y + bb4.y;
                z.z = a.z + b.z + f * wf4.z + bb4.z;
                z.w = a.w + b.w + f * wf4.w + bb4.w;
                z.x = z.x >= 0.f ? z.x : NEG * z.x;
                z.y = z.y >= 0.f ? z.y : NEG * z.y;
                z.z = z.z >= 0.f ? z.z : NEG * z.z;
                z.w = z.w >= 0.f ? z.w : NEG * z.w;
            }
            float* zd = &z0sD[cl * Z0STRIDE + 2 * j];
            ((float4*)zd)[0] = make_float4(z.x, z.x, z.y, z.y);
            ((float4*)zd)[1] = make_float4(z.z, z.z, z.w, z.w);
        }
    }
    __syncthreads();

    {
        int oc = tid & 15, cg = tid >> 4;
        int ob = oc * 4;
        unsigned long long a01[4] = {0ull, 0ull, 0ull, 0ull};
        unsigned long long a23[4] = {0ull, 0ull, 0ull, 0ull};
        const float* z0 = &z0sD[(cg * 4 + 0) * Z0STRIDE];
        const float* z1 = &z0sD[(cg * 4 + 1) * Z0STRIDE];
        const float* z2 = &z0sD[(cg * 4 + 2) * Z0STRIDE];
        const float* z3 = &z0sD[(cg * 4 + 3) * Z0STRIDE];
#pragma unroll 8
        for (int k = 0; k < 64; k++) {
            ulonglong2 wp = *(const ulonglong2*)&w1s[k * 64 + ob];
            unsigned long long q0 = *(const unsigned long long*)(z0 + 2 * k);
            unsigned long long q1 = *(const unsigned long long*)(z1 + 2 * k);
            unsigned long long q2 = *(const unsigned long long*)(z2 + 2 * k);
            unsigned long long q3 = *(const unsigned long long*)(z3 + 2 * k);
            FMA2(a01[0], q0, wp.x); FMA2(a23[0], q0, wp.y);
            FMA2(a01[1], q1, wp.x); FMA2(a23[1], q1, wp.y);
            FMA2(a01[2], q2, wp.x); FMA2(a23[2], q2, wp.y);
            FMA2(a01[3], q3, wp.x); FMA2(a23[3], q3, wp.y);
        }
        float4 bb = *(const float4*)&b1s[ob];
        float4 w2v = *(const float4*)&w2s[ob];
        float part[4];
#pragma unroll
        for (int q = 0; q < 4; q++) {
            float t0, t1, t2, t3;
            UNPACK2(t0, t1, a01[q]);
            UNPACK2(t2, t3, a23[q]);
            t0 += bb.x; t0 = t0 >= 0.f ? t0 : NEG * t0;
            t1 += bb.y; t1 = t1 >= 0.f ? t1 : NEG * t1;
            t2 += bb.z; t2 = t2 >= 0.f ? t2 : NEG * t2;
            t3 += bb.w; t3 = t3 >= 0.f ? t3 : NEG * t3;
            part[q] = t0 * w2v.x + t1 * w2v.y + t2 * w2v.z + t3 * w2v.w;
        }
#pragma unroll
        for (int q = 0; q < 4; q++) {
#pragma unroll
            for (int o = 8; o; o >>= 1)
                part[q] += __shfl_xor_sync(0xffffffffu, part[q], o);
        }
        if (oc == 0) {
#pragma unroll
            for (int q = 0; q < 4; q++) {
                int gc = base + cg * 4 + q;
                if (gc < C) y[gc] = part[q] + b2s[0];
            }
        }
    }
}

// ---------------- softmax (2 kernels, deterministic) ----------------
__global__ void k_softA(const float* __restrict__ y, int C) {
    __shared__ float mm[256], ss[256];
    float m = -3.402823466e38f, s = 0.f;
    for (int i = blockIdx.x * 256 + threadIdx.x; i < C; i += gridDim.x * 256) {
        float v = y[i];
        if (v > m) { s = s * expf(m - v) + 1.0f; m = v; }
        else s += expf(v - m);
    }
    mm[threadIdx.x] = m; ss[threadIdx.x] = s;
    __syncthreads();
    for (int st = 128; st; st >>= 1) {
        if (threadIdx.x < st) {
            float m2 = mm[threadIdx.x + st], s2 = ss[threadIdx.x + st];
            float M = fmaxf(mm[threadIdx.x], m2);
            ss[threadIdx.x] = ss[threadIdx.x] * expf(mm[threadIdx.x] - M) + s2 * expf(m2 - M);
            mm[threadIdx.x] = M;
        }
        __syncthreads();
    }
    if (threadIdx.x == 0) { g_part[blockIdx.x] = mm[0]; g_part[128 + blockIdx.x] = ss[0]; }
}

__global__ void k_softFin(const float* __restrict__ y, float* __restrict__ out, int C) {
    __shared__ float mm[128], ss[128];
    int t = threadIdx.x;
    if (t < 128) { mm[t] = g_part[t]; ss[t] = g_part[128 + t]; }
    __syncthreads();
    for (int st = 64; st; st >>= 1) {
        if (t < st) {
            float m2 = mm[t + st], s2 = ss[t + st];
            float M = fmaxf(mm[t], m2);
            ss[t] = ss[t] * expf(mm[t] - M) + s2 * expf(m2 - M);
            mm[t] = M;
        }
        __syncthreads();
    }
    float mx = mm[0];
    float inv = 1.0f / ss[0];
    for (int i = blockIdx.x * 256 + t; i < C; i += gridDim.x * 256)
        out[i] = expf(y[i] - mx) * inv;
}

// ---------------- host launcher ----------------
extern "C" void kernel_launch(void* const* d_in, const int* in_sizes, int n_in,
                              void* d_out, int out_size) {
    const float* x   = (const float*)d_in[0];
    const int* src   = (const int*)d_in[1];
    const int* dst   = (const int*)d_in[2];
    const int* cu    = (const int*)d_in[3];
    const int* cv    = (const int*)d_in[4];
    const float* cf  = (const float*)d_in[5];
    const float* ws0 = (const float*)d_in[6];
    const float* wn0 = (const float*)d_in[7];
    const float* b0  = (const float*)d_in[8];
    const float* ga0 = (const float*)d_in[9];
    const float* be0 = (const float*)d_in[10];
    const float* rm0 = (const float*)d_in[11];
    const float* rv0 = (const float*)d_in[12];
    const float* ws1 = (const float*)d_in[13];
    const float* wn1 = (const float*)d_in[14];
    const float* b1  = (const float*)d_in[15];
    const float* ga1 = (const float*)d_in[16];
    const float* be1 = (const float*)d_in[17];
    const float* rm1 = (const float*)d_in[18];
    const float* rv1 = (const float*)d_in[19];
    const float* mw0 = (const float*)d_in[20];
    const float* mb0 = (const float*)d_in[21];
    const float* mw1 = (const float*)d_in[22];
    const float* mb1 = (const float*)d_in[23];
    const float* mw2 = (const float*)d_in[24];
    const float* mb2 = (const float*)d_in[25];

    int E = in_sizes[1];
    int C = in_sizes[3];
    float* y = (float*)d_out;
    float* soft = y + C;

    float *h0p, *h1p, *aggp, *pup, *pvp;
    cudaGetSymbolAddress((void**)&h0p, g_h0);
    cudaGetSymbolAddress((void**)&h1p, g_h1);
    cudaGetSymbolAddress((void**)&aggp, g_agg);
    cudaGetSymbolAddress((void**)&pup, g_pu);
    cudaGetSymbolAddress((void**)&pvp, g_pv);

    cudaFuncSetAttribute(k_gemm, cudaFuncAttributeMaxDynamicSharedMemorySize, 196608);
    cudaFuncSetAttribute(k_prep, cudaFuncAttributeMaxDynamicSharedMemorySize, 131072);
    cudaFuncSetAttribute(k_cand, cudaFuncAttributeMaxDynamicSharedMemorySize, CAND_SMEM_FLOATS * 4);

    // 1: zero state
    k_zero<<<(Nn + 255) / 256, 256>>>();
    // 2: degree count
    k_count<<<1024, 256>>>(dst, E);
    // 3: scan + fill (single pass)
    k_scanfill<<<NB_SCAN, 1024>>>(src, dst, E);
    // 4: agg layer 0
    k_agg<<<(Nn + 7) / 8, 256>>>(x, aggp);
    // 5: gemm layer 0
    k_gemm<<<(Nn + 63) / 64, 512, 196608>>>(x, aggp, ws0, wn0, b0, ga0, be0, rm0, rv0, h0p, 0);
    // 6: agg layer 1
    k_agg<<<(Nn + 7) / 8, 256>>>(h0p, aggp);
    // 7: gemm layer 1 (+ nan_to_num)
    k_gemm<<<(Nn + 63) / 64, 512, 196608>>>(h0p, aggp, ws1, wn1, b1, ga1, be1, rm1, rv1, h1p, 1);
    // 8: MLP layer0 hoisted to node level
    k_prep<<<(Nn + 63) / 64, 512, 131072>>>(h1p, mw0, pup, pvp);
    // 9: candidate tail -> y
    k_cand<<<(C + 63) / 64, 256, CAND_SMEM_FLOATS * 4>>>(pup, pvp, cu, cv, cf, mw0, mb0, mw1, mb1, mw2, mb2, y, C);
    // 10,11: softmax
    k_softA<<<128, 256>>>(y, C);
    k_softFin<<<256, 256>>>(y, soft, C);
}

// round 13
// speedup vs baseline: 1.0729x; 1.0729x over previous
#include <cuda_runtime.h>
#include <math.h>

#define Nn 50000
#define Ee 800000
#define Cc 100000
#define D 128
#define NEG 0.01f
#define BN_EPS 1e-5f
#define NB_CSR 148

#define FMA2(d, a, b) asm("fma.rn.f32x2 %0, %1, %2, %0;" : "+l"(d) : "l"(a), "l"(b))
#define UNPACK2(lo, hi, v) asm("mov.b64 {%0, %1}, %2;" : "=f"(lo), "=f"(hi) : "l"(v))

// ---------------- scratch (static __device__, no allocation) ----------------
__device__ float g_h0[(size_t)Nn * D];
__device__ float g_h1[(size_t)Nn * D];
__device__ float g_agg[(size_t)Nn * D];
__device__ float g_pu[(size_t)Nn * 64];
__device__ float g_pv[(size_t)Nn * 64];
__device__ int   g_deg[Nn];
__device__ int   g_off[Nn + 1];
__device__ int   g_cur[Nn];
__device__ int   g_csr[Ee];
__device__ unsigned long long g_lb[NB_CSR];  // lookback: (aggregate<<1)|1
__device__ unsigned int g_bar[4];
__device__ float g_part[256];

// ---------------- zero state (also resets grid-barrier counters each call) ----------------
__global__ void k_zero() {
    int i = blockIdx.x * blockDim.x + threadIdx.x;
    if (i < Nn) g_deg[i] = 0;
    if (i < NB_CSR) g_lb[i] = 0ull;
    if (i < 4) g_bar[i] = 0u;
}

// ---------------- merged: count + scan (lookback) + fill; 148 co-resident blocks ----------------
__device__ __forceinline__ void gbar(unsigned int* ctr) {
    __threadfence();
    __syncthreads();
    if (threadIdx.x == 0) {
        atomicAdd(ctr, 1u);
        while (atomicAdd(ctr, 0u) < (unsigned)NB_CSR) {}
    }
    __syncthreads();
}

__global__ void k_csr(const int* __restrict__ src, const int* __restrict__ dst, int E) {
    __shared__ int ws[32];
    __shared__ int preds[NB_CSR];
    __shared__ int sbase;
    int b = blockIdx.x;
    int tid = threadIdx.x;
    int lane = tid & 31, wid = tid >> 5;
    int gstride = NB_CSR * 1024;

    // phase 0: degree count
    for (int e = b * 1024 + tid; e < E; e += gstride)
        atomicAdd(&g_deg[dst[e]], 1);
    gbar(&g_bar[0]);

    // phase 1: scan (blocks 0..48 own elements; all publish aggregates)
    int i = b * 1024 + tid;
    int v = (i < Nn) ? g_deg[i] : 0;
    int s = v;
#pragma unroll
    for (int o = 1; o < 32; o <<= 1) {
        int t = __shfl_up_sync(0xffffffffu, s, o);
        if (lane >= o) s += t;
    }
    if (lane == 31) ws[wid] = s;
    __syncthreads();
    if (wid == 0) {
        int t = ws[lane];
#pragma unroll
        for (int o = 1; o < 32; o <<= 1) {
            int u = __shfl_up_sync(0xffffffffu, t, o);
            if (lane >= o) t += u;
        }
        ws[lane] = t;
    }
    __syncthreads();
    s += wid ? ws[wid - 1] : 0;  // local inclusive

    if (tid == 1023)
        atomicExch(&g_lb[b], (((unsigned long long)(unsigned)s) << 1) | 1ull);
    if (tid < b) {
        unsigned long long x;
        do { x = atomicAdd(&g_lb[tid], 0ull); } while (!(x & 1ull));
        preds[tid] = (int)(x >> 1);
    }
    __syncthreads();
    if (tid == 0) {
        int acc = 0;
        for (int j = 0; j < b; j++) acc += preds[j];
        sbase = acc;
    }
    __syncthreads();
    s += sbase;

    if (i < Nn) {
        g_off[i + 1] = s;
        g_cur[i] = s - v;
    }
    if (i == 0) g_off[0] = 0;
    gbar(&g_bar[1]);

    // phase 2: CSR fill
    for (int e = b * 1024 + tid; e < E; e += gstride) {
        int d = dst[e];
        int p = atomicAdd(&g_cur[d], 1);
        g_csr[p] = src[e];
    }
}

// ---------------- segment-mean aggregation (warp per node, no smem, high occ) ----------------
__global__ void k_agg(const float* __restrict__ A, float* __restrict__ out) {
    int w = threadIdx.x >> 5, l = threadIdx.x & 31;
    int node = blockIdx.x * 8 + w;
    if (node >= Nn) return;
    int s = g_off[node], e = g_off[node + 1];
    int deg = e - s;
    float4 a0 = make_float4(0.f, 0.f, 0.f, 0.f);
    float4 a1 = make_float4(0.f, 0.f, 0.f, 0.f);
    float4 a2 = make_float4(0.f, 0.f, 0.f, 0.f);
    float4 a3 = make_float4(0.f, 0.f, 0.f, 0.f);
    for (int base = s; base < e; base += 32) {
        int cnt = e - base; if (cnt > 32) cnt = 32;
        int idx = (l < cnt) ? g_csr[base + l] : 0;
        int j = 0;
        for (; j + 4 <= cnt; j += 4) {
            int r0 = __shfl_sync(0xffffffffu, idx, j);
            int r1 = __shfl_sync(0xffffffffu, idx, j + 1);
            int r2 = __shfl_sync(0xffffffffu, idx, j + 2);
            int r3 = __shfl_sync(0xffffffffu, idx, j + 3);
            float4 v0 = ((const float4*)(A + (size_t)r0 * D))[l];
            float4 v1 = ((const float4*)(A + (size_t)r1 * D))[l];
            float4 v2 = ((const float4*)(A + (size_t)r2 * D))[l];
            float4 v3 = ((const float4*)(A + (size_t)r3 * D))[l];
            a0.x += v0.x; a0.y += v0.y; a0.z += v0.z; a0.w += v0.w;
            a1.x += v1.x; a1.y += v1.y; a1.z += v1.z; a1.w += v1.w;
            a2.x += v2.x; a2.y += v2.y; a2.z += v2.z; a2.w += v2.w;
            a3.x += v3.x; a3.y += v3.y; a3.z += v3.z; a3.w += v3.w;
        }
        for (; j < cnt; j++) {
            int r = __shfl_sync(0xffffffffu, idx, j);
            float4 vv = ((const float4*)(A + (size_t)r * D))[l];
            a0.x += vv.x; a0.y += vv.y; a0.z += vv.z; a0.w += vv.w;
        }
    }
    a0.x += a1.x + a2.x + a3.x;
    a0.y += a1.y + a2.y + a3.y;
    a0.z += a1.z + a2.z + a3.z;
    a0.w += a1.w + a2.w + a3.w;
    float inv = 1.0f / (float)(deg > 1 ? deg : 1);
    a0.x *= inv; a0.y *= inv; a0.z *= inv; a0.w *= inv;
    ((float4*)(out + (size_t)node * D))[l] = a0;
}

// ---------------- persistent dual GEMM + BN + leaky (k-pair f32x2, pair-packed) ----------------
// grid = 148 blocks, 512 threads, 192KB smem. Weights staged ONCE, loop over 64-node tiles.
#define GEMM_TILES ((Nn + 63) / 64)
__global__ void k_gemm(const float* __restrict__ A, const float* __restrict__ G,
                       const float* __restrict__ Ws, const float* __restrict__ Wn,
                       const float* __restrict__ bias, const float* __restrict__ gamma,
                       const float* __restrict__ beta, const float* __restrict__ rm,
                       const float* __restrict__ rv, float* __restrict__ out, int fixnan) {
    extern __shared__ float sm[];
    float* sWsP = sm;               // [0, 16384)
    float* sWnP = sm + 16384;       // [16384, 32768)
    float* sVal = sm + 32768;       // [32768, 49152)  pair stride 512
    for (int idx = threadIdx.x; idx < 4096; idx += 512) {
        int kp = idx >> 6;
        int cg = idx & 63;
        float2 a0 = *(const float2*)&Ws[(2 * kp) * 128 + 2 * cg];
        float2 b0 = *(const float2*)&Ws[(2 * kp + 1) * 128 + 2 * cg];
        *(float4*)&sWsP[(kp * 128 + 2 * cg) * 2] = make_float4(a0.x, b0.x, a0.y, b0.y);
        float2 a1 = *(const float2*)&Wn[(2 * kp) * 128 + 2 * cg];
        float2 b1 = *(const float2*)&Wn[(2 * kp + 1) * 128 + 2 * cg];
        *(float4*)&sWnP[(kp * 128 + 2 * cg) * 2] = make_float4(a1.x, b1.x, a1.y, b1.y);
    }
    __syncthreads();

    int w = threadIdx.x >> 5, l = threadIdx.x & 31;
    int g = w >> 1, h = w & 1;
    int c0 = 64 * h + 2 * l;
    float2 bb = *(const float2*)&bias[c0];
    float2 ga = *(const float2*)&gamma[c0];
    float2 be = *(const float2*)&beta[c0];
    float2 rmv = *(const float2*)&rm[c0];
    float2 rvv = *(const float2*)&rv[c0];
    float scl0 = ga.x * rsqrtf(rvv.x + BN_EPS), shf0 = be.x - rmv.x * scl0;
    float scl1 = ga.y * rsqrtf(rvv.y + BN_EPS), shf1 = be.y - rmv.y * scl1;

    for (int tile = blockIdx.x; tile < GEMM_TILES; tile += 148) {
        int blockBase = tile * 64;
        // stage values pair-packed: x at sVal[p*512 + kp*4], a at +256
#pragma unroll
        for (int pr = 0; pr < 2; pr++) {
            int p = w * 2 + pr;
            int nA = blockBase + p * 2, nB = nA + 1;
            float4 xA = make_float4(0.f, 0.f, 0.f, 0.f), xB = xA, aA = xA, aB = xA;
            if (nA < Nn) {
                xA = ((const float4*)(A + (size_t)nA * D))[l];
                aA = ((const float4*)(G + (size_t)nA * D))[l];
            }
            if (nB < Nn) {
                xB = ((const float4*)(A + (size_t)nB * D))[l];
                aB = ((const float4*)(G + (size_t)nB * D))[l];
            }
            float* bx = sVal + p * 512;
            *(float4*)(bx + 8 * l)           = make_float4(xA.x, xA.y, xB.x, xB.y);
            *(float4*)(bx + 8 * l + 4)       = make_float4(xA.z, xA.w, xB.z, xB.w);
            *(float4*)(bx + 256 + 8 * l)     = make_float4(aA.x, aA.y, aB.x, aB.y);
            *(float4*)(bx + 256 + 8 * l + 4) = make_float4(aA.z, aA.w, aB.z, aB.w);
        }
        __syncthreads();

        const float* wsb = sWsP + 128 * h + 4 * l;
        const float* wnb = sWnP + 128 * h + 4 * l;
        const float* vb = sVal + g * 4 * 512;
        unsigned long long acc[8][2];
#pragma unroll
        for (int n = 0; n < 8; n++) { acc[n][0] = 0ull; acc[n][1] = 0ull; }
#pragma unroll 4
        for (int kp = 0; kp < 64; kp++) {
            ulonglong2 wS = *(const ulonglong2*)(wsb + kp * 256);
            ulonglong2 wN = *(const ulonglong2*)(wnb + kp * 256);
#pragma unroll
            for (int p = 0; p < 4; p++) {
                ulonglong2 vx = *(const ulonglong2*)(vb + p * 512 + kp * 4);
                ulonglong2 va = *(const ulonglong2*)(vb + p * 512 + 256 + kp * 4);
                FMA2(acc[2 * p][0], vx.x, wS.x);     FMA2(acc[2 * p][1], vx.x, wS.y);
                FMA2(acc[2 * p + 1][0], vx.y, wS.x); FMA2(acc[2 * p + 1][1], vx.y, wS.y);
                FMA2(acc[2 * p][0], va.x, wN.x);     FMA2(acc[2 * p][1], va.x, wN.y);
                FMA2(acc[2 * p + 1][0], va.y, wN.x); FMA2(acc[2 * p + 1][1], va.y, wN.y);
            }
        }

#pragma unroll
        for (int n = 0; n < 8; n++) {
            int node = blockBase + 8 * g + n;
            if (node >= Nn) continue;
            float pe, po;
            UNPACK2(pe, po, acc[n][0]);
            float v0 = (pe + po) + bb.x;
            v0 = v0 * scl0 + shf0;
            v0 = v0 >= 0.f ? v0 : NEG * v0;
            UNPACK2(pe, po, acc[n][1]);
            float v1 = (pe + po) + bb.y;
            v1 = v1 * scl1 + shf1;
            v1 = v1 >= 0.f ? v1 : NEG * v1;
            if (fixnan) {
                if (isnan(v0)) v0 = 1e-14f;
                else if (isinf(v0)) v0 = v0 > 0.f ? 3.402823466e38f : -3.402823466e38f;
                if (isnan(v1)) v1 = 1e-14f;
                else if (isinf(v1)) v1 = v1 > 0.f ? 3.402823466e38f : -3.402823466e38f;
            }
            *(float2*)&out[(size_t)node * D + c0] = make_float2(v0, v1);
        }
        __syncthreads();
    }
}

// ---------------- persistent node-level MLP layer0 projection (f32x2) ----------------
__global__ void k_prep(const float* __restrict__ h, const float* __restrict__ mw0,
                       float* __restrict__ pu, float* __restrict__ pv) {
    extern __shared__ float sm[];
    float* sWI = sm;            // [0, 16384)
    float* sVal = sm + 16384;   // [16384, 32768)  node stride 256
    for (int idx = threadIdx.x; idx < 4096; idx += 512) {
        int k = idx >> 5, p = idx & 31;
        float2 u = *(const float2*)&mw0[k * 64 + 2 * p];
        float2 v = *(const float2*)&mw0[(128 + k) * 64 + 2 * p];
        *(float4*)&sWI[k * 128 + p * 4] = make_float4(u.x, u.y, v.x, v.y);
    }
    __syncthreads();

    int w = threadIdx.x >> 5, l = threadIdx.x & 31;
    int nl0 = w * 4;

    for (int tile = blockIdx.x; tile < GEMM_TILES; tile += 148) {
        int n0 = tile * 64 + nl0;
#pragma unroll
        for (int t = 0; t < 4; t++) {
            int node = n0 + t;
            float4 xv = make_float4(0.f, 0.f, 0.f, 0.f);
            if (node < Nn) xv = ((const float4*)(h + (size_t)node * D))[l];
            float4* sd = (float4*)(sVal + (nl0 + t) * 256 + l * 8);
            sd[0] = make_float4(xv.x, xv.x, xv.y, xv.y);
            sd[1] = make_float4(xv.z, xv.z, xv.w, xv.w);
        }
        __syncwarp();

        unsigned long long au[4] = {0ull, 0ull, 0ull, 0ull};
        unsigned long long av[4] = {0ull, 0ull, 0ull, 0ull};
        const float* wib = sWI + l * 4;
        const float* vb = sVal + nl0 * 256;
#pragma unroll 8
        for (int k = 0; k < 128; k++) {
            ulonglong2 wp = *(const ulonglong2*)(wib + k * 128);
#pragma unroll
            for (int t = 0; t < 4; t++) {
                unsigned long long xd = *(const unsigned long long*)(vb + t * 256 + 2 * k);
                FMA2(au[t], xd, wp.x);
                FMA2(av[t], xd, wp.y);
            }
        }
#pragma unroll
        for (int t = 0; t < 4; t++) {
            int node = n0 + t;
            if (node >= Nn) continue;
            *(float2*)&pu[(size_t)node * 64 + 2 * l] = *(float2*)&au[t];
            *(float2*)&pv[(size_t)node * 64 + 2 * l] = *(float2*)&av[t];
        }
        __syncwarp();
    }
}

// ---------------- candidate kernel ----------------
#define Z0STRIDE 136
#define CAND_SMEM_FLOATS 13060
__global__ void k_cand(const float* __restrict__ pu, const float* __restrict__ pv,
                       const int* __restrict__ cu, const int* __restrict__ cv,
                       const float* __restrict__ cf,
                       const float* __restrict__ mw0, const float* __restrict__ mb0,
                       const float* __restrict__ mw1, const float* __restrict__ mb1,
                       const float* __restrict__ mw2, const float* __restrict__ mb2,
                       float* __restrict__ y, int C) {
    extern __shared__ float smc[];
    float* w1s = smc;
    float* z0sD = smc + 4096;
    float* wfs = smc + 12800;
    float* b0s = smc + 12864;
    float* b1s = smc + 12928;
    float* w2s = smc + 12992;
    float* b2s = smc + 13056;
    int tid = threadIdx.x;
    for (int i = tid; i < 4096; i += 256) w1s[i] = mw1[i];
    if (tid < 64) {
        wfs[tid] = mw0[256 * 64 + tid];
        b0s[tid] = mb0[tid];
        b1s[tid] = mb1[tid];
        w2s[tid] = mw2[tid];
    }
    if (tid == 0) b2s[0] = mb2[0];
    __syncthreads();

    int base = blockIdx.x * 64;

    {
        int jc = tid & 15, j = jc * 4;
        int c0 = tid >> 4;
#pragma unroll
        for (int i = 0; i < 4; i++) {
            int cl = c0 + 16 * i;
            int gc = base + cl;
            float4 z = make_float4(0.f, 0.f, 0.f, 0.f);
            if (gc < C) {
                int u = cu[gc], v = cv[gc];
                float f = cf[gc];
                float4 a = *(const float4*)&pu[(size_t)u * 64 + j];
                float4 b = *(const float4*)&pv[(size_t)v * 64 + j];
                float4 wf4 = *(const float4*)&wfs[j];
                float4 bb4 = *(const float4*)&b0s[j];
                z.x = a.x + b.x + f * wf4.x + bb4.x;
                z.y = a.y + b.y + f * wf4.y + bb4.y;
                z.z = a.z + b.z + f * wf4.z + bb4.z;
                z.w = a.w + b.w + f * wf4.w + bb4.w;
                z.x = z.x >= 0.f ? z.x : NEG * z.x;
                z.y = z.y >= 0.f ? z.y : NEG * z.y;
                z.z = z.z >= 0.f ? z.z : NEG * z.z;
                z.w = z.w >= 0.f ? z.w : NEG * z.w;
            }
            float* zd = &z0sD[cl * Z0STRIDE + 2 * j];
            ((float4*)zd)[0] = make_float4(z.x, z.x, z.y, z.y);
            ((float4*)zd)[1] = make_float4(z.z, z.z, z.w, z.w);
        }
    }
    __syncthreads();

    {
        int oc = tid & 15, cg = tid >> 4;
        int ob = oc * 4;
        unsigned long long a01[4] = {0ull, 0ull, 0ull, 0ull};
        unsigned long long a23[4] = {0ull, 0ull, 0ull, 0ull};
        const float* z0 = &z0sD[(cg * 4 + 0) * Z0STRIDE];
        const float* z1 = &z0sD[(cg * 4 + 1) * Z0STRIDE];
        const float* z2 = &z0sD[(cg * 4 + 2) * Z0STRIDE];
        const float* z3 = &z0sD[(cg * 4 + 3) * Z0STRIDE];
#pragma unroll 8
        for (int k = 0; k < 64; k++) {
            ulonglong2 wp = *(const ulonglong2*)&w1s[k * 64 + ob];
            unsigned long long q0 = *(const unsigned long long*)(z0 + 2 * k);
            unsigned long long q1 = *(const unsigned long long*)(z1 + 2 * k);
            unsigned long long q2 = *(const unsigned long long*)(z2 + 2 * k);
            unsigned long long q3 = *(const unsigned long long*)(z3 + 2 * k);
            FMA2(a01[0], q0, wp.x); FMA2(a23[0], q0, wp.y);
            FMA2(a01[1], q1, wp.x); FMA2(a23[1], q1, wp.y);
            FMA2(a01[2], q2, wp.x); FMA2(a23[2], q2, wp.y);
            FMA2(a01[3], q3, wp.x); FMA2(a23[3], q3, wp.y);
        }
        float4 bb = *(const float4*)&b1s[ob];
        float4 w2v = *(const float4*)&w2s[ob];
        float part[4];
#pragma unroll
        for (int q = 0; q < 4; q++) {
            float t0, t1, t2, t3;
            UNPACK2(t0, t1, a01[q]);
            UNPACK2(t2, t3, a23[q]);
            t0 += bb.x; t0 = t0 >= 0.f ? t0 : NEG * t0;
            t1 += bb.y; t1 = t1 >= 0.f ? t1 : NEG * t1;
            t2 += bb.z; t2 = t2 >= 0.f ? t2 : NEG * t2;
            t3 += bb.w; t3 = t3 >= 0.f ? t3 : NEG * t3;
            part[q] = t0 * w2v.x + t1 * w2v.y + t2 * w2v.z + t3 * w2v.w;
        }
#pragma unroll
        for (int q = 0; q < 4; q++) {
#pragma unroll
            for (int o = 8; o; o >>= 1)
                part[q] += __shfl_xor_sync(0xffffffffu, part[q], o);
        }
        if (oc == 0) {
#pragma unroll
            for (int q = 0; q < 4; q++) {
                int gc = base + cg * 4 + q;
                if (gc < C) y[gc] = part[q] + b2s[0];
            }
        }
    }
}

// ---------------- softmax (2 kernels, deterministic) ----------------
__global__ void k_softA(const float* __restrict__ y, int C) {
    __shared__ float mm[256], ss[256];
    float m = -3.402823466e38f, s = 0.f;
    for (int i = blockIdx.x * 256 + threadIdx.x; i < C; i += gridDim.x * 256) {
        float v = y[i];
        if (v > m) { s = s * expf(m - v) + 1.0f; m = v; }
        else s += expf(v - m);
    }
    mm[threadIdx.x] = m; ss[threadIdx.x] = s;
    __syncthreads();
    for (int st = 128; st; st >>= 1) {
        if (threadIdx.x < st) {
            float m2 = mm[threadIdx.x + st], s2 = ss[threadIdx.x + st];
            float M = fmaxf(mm[threadIdx.x], m2);
            ss[threadIdx.x] = ss[threadIdx.x] * expf(mm[threadIdx.x] - M) + s2 * expf(m2 - M);
            mm[threadIdx.x] = M;
        }
        __syncthreads();
    }
    if (threadIdx.x == 0) { g_part[blockIdx.x] = mm[0]; g_part[128 + blockIdx.x] = ss[0]; }
}

__global__ void k_softFin(const float* __restrict__ y, float* __restrict__ out, int C) {
    __shared__ float mm[128], ss[128];
    int t = threadIdx.x;
    if (t < 128) { mm[t] = g_part[t]; ss[t] = g_part[128 + t]; }
    __syncthreads();
    for (int st = 64; st; st >>= 1) {
        if (t < st) {
            float m2 = mm[t + st], s2 = ss[t + st];
            float M = fmaxf(mm[t], m2);
            ss[t] = ss[t] * expf(mm[t] - M) + s2 * expf(m2 - M);
            mm[t] = M;
        }
        __syncthreads();
    }
    float mx = mm[0];
    float inv = 1.0f / ss[0];
    for (int i = blockIdx.x * 256 + t; i < C; i += gridDim.x * 256)
        out[i] = expf(y[i] - mx) * inv;
}

// ---------------- host launcher ----------------
extern "C" void kernel_launch(void* const* d_in, const int* in_sizes, int n_in,
                              void* d_out, int out_size) {
    const float* x   = (const float*)d_in[0];
    const int* src   = (const int*)d_in[1];
    const int* dst   = (const int*)d_in[2];
    const int* cu    = (const int*)d_in[3];
    const int* cv    = (const int*)d_in[4];
    const float* cf  = (const float*)d_in[5];
    const float* ws0 = (const float*)d_in[6];
    const float* wn0 = (const float*)d_in[7];
    const float* b0  = (const float*)d_in[8];
    const float* ga0 = (const float*)d_in[9];
    const float* be0 = (const float*)d_in[10];
    const float* rm0 = (const float*)d_in[11];
    const float* rv0 = (const float*)d_in[12];
    const float* ws1 = (const float*)d_in[13];
    const float* wn1 = (const float*)d_in[14];
    const float* b1  = (const float*)d_in[15];
    const float* ga1 = (const float*)d_in[16];
    const float* be1 = (const float*)d_in[17];
    const float* rm1 = (const float*)d_in[18];
    const float* rv1 = (const float*)d_in[19];
    const float* mw0 = (const float*)d_in[20];
    const float* mb0 = (const float*)d_in[21];
    const float* mw1 = (const float*)d_in[22];
    const float* mb1 = (const float*)d_in[23];
    const float* mw2 = (const float*)d_in[24];
    const float* mb2 = (const float*)d_in[25];

    int E = in_sizes[1];
    int C = in_sizes[3];
    float* y = (float*)d_out;
    float* soft = y + C;

    float *h0p, *h1p, *aggp, *pup, *pvp;
    cudaGetSymbolAddress((void**)&h0p, g_h0);
    cudaGetSymbolAddress((void**)&h1p, g_h1);
    cudaGetSymbolAddress((void**)&aggp, g_agg);
    cudaGetSymbolAddress((void**)&pup, g_pu);
    cudaGetSymbolAddress((void**)&pvp, g_pv);

    cudaFuncSetAttribute(k_gemm, cudaFuncAttributeMaxDynamicSharedMemorySize, 196608);
    cudaFuncSetAttribute(k_prep, cudaFuncAttributeMaxDynamicSharedMemorySize, 131072);
    cudaFuncSetAttribute(k_cand, cudaFuncAttributeMaxDynamicSharedMemorySize, CAND_SMEM_FLOATS * 4);

    // 1: zero state (incl. barrier counters)
    k_zero<<<(Nn + 255) / 256, 256>>>();
    // 2: count + scan + fill (merged, 148 co-resident blocks)
    k_csr<<<NB_CSR, 1024>>>(src, dst, E);
    // 3: agg layer 0
    k_agg<<<(Nn + 7) / 8, 256>>>(x, aggp);
    // 4: gemm layer 0 (PROFILED SLOT)
    k_gemm<<<148, 512, 196608>>>(x, aggp, ws0, wn0, b0, ga0, be0, rm0, rv0, h0p, 0);
    // 5: agg layer 1
    k_agg<<<(Nn + 7) / 8, 256>>>(h0p, aggp);
    // 6: gemm layer 1 (+ nan_to_num)
    k_gemm<<<148, 512, 196608>>>(h0p, aggp, ws1, wn1, b1, ga1, be1, rm1, rv1, h1p, 1);
    // 7: MLP layer0 hoisted to node level (persistent)
    k_prep<<<148, 512, 131072>>>(h1p, mw0, pup, pvp);
    // 8: candidate tail -> y
    k_cand<<<(C + 63) / 64, 256, CAND_SMEM_FLOATS * 4>>>(pup, pvp, cu, cv, cf, mw0, mb0, mw1, mb1, mw2, mb2, y, C);
    // 9,10: softmax
    k_softA<<<128, 256>>>(y, C);
    k_softFin<<<256, 256>>>(y, soft, C);
}

// round 14
// speedup vs baseline: 1.0937x; 1.0194x over previous
#include <cuda_runtime.h>
#include <math.h>

#define Nn 50000
#define Ee 800000
#define Cc 100000
#define D 128
#define NEG 0.01f
#define BN_EPS 1e-5f
#define NB_CSR 148
#define NT96 ((Nn + 95) / 96)

#define FMA2(d, a, b) asm("fma.rn.f32x2 %0, %1, %2, %0;" : "+l"(d) : "l"(a), "l"(b))
#define UNPACK2(lo, hi, v) asm("mov.b64 {%0, %1}, %2;" : "=f"(lo), "=f"(hi) : "l"(v))

// ---------------- scratch (static __device__, no allocation) ----------------
__device__ float g_h0[(size_t)Nn * D];
__device__ float g_h1[(size_t)Nn * D];
__device__ float g_agg[(size_t)Nn * D];
__device__ float g_pu[(size_t)Nn * 64];
__device__ float g_pv[(size_t)Nn * 64];
__device__ int   g_deg[Nn];
__device__ int   g_off[Nn + 1];
__device__ int   g_cur[Nn];
__device__ int   g_csr[Ee];
__device__ unsigned long long g_lb[NB_CSR];
__device__ unsigned int g_bar[8];
__device__ float g_part[256];

// ---------------- tiny reset (barrier counters + lookback flags) ----------------
__global__ void k_zero() {
    int i = threadIdx.x;
    if (i < NB_CSR) g_lb[i] = 0ull;
    if (i < 8) g_bar[i] = 0u;
}

// ---------------- merged: zero-deg + count + scan + fill; 148 co-resident blocks ----------------
__device__ __forceinline__ void gbar(unsigned int* ctr) {
    __threadfence();
    __syncthreads();
    if (threadIdx.x == 0) {
        atomicAdd(ctr, 1u);
        while (atomicAdd(ctr, 0u) < (unsigned)NB_CSR) {}
    }
    __syncthreads();
}

__global__ void k_csr(const int* __restrict__ src, const int* __restrict__ dst, int E) {
    __shared__ int ws[32];
    __shared__ int preds[NB_CSR];
    __shared__ int sbase;
    int b = blockIdx.x;
    int tid = threadIdx.x;
    int lane = tid & 31, wid = tid >> 5;
    int gstride = NB_CSR * 1024;

    // phase 0: zero degrees
    for (int i = b * 1024 + tid; i < Nn; i += gstride) g_deg[i] = 0;
    gbar(&g_bar[0]);

    // phase 1: degree count
    for (int e = b * 1024 + tid; e < E; e += gstride)
        atomicAdd(&g_deg[dst[e]], 1);
    gbar(&g_bar[1]);

    // phase 2: scan
    int i = b * 1024 + tid;
    int v = (i < Nn) ? g_deg[i] : 0;
    int s = v;
#pragma unroll
    for (int o = 1; o < 32; o <<= 1) {
        int t = __shfl_up_sync(0xffffffffu, s, o);
        if (lane >= o) s += t;
    }
    if (lane == 31) ws[wid] = s;
    __syncthreads();
    if (wid == 0) {
        int t = ws[lane];
#pragma unroll
        for (int o = 1; o < 32; o <<= 1) {
            int u = __shfl_up_sync(0xffffffffu, t, o);
            if (lane >= o) t += u;
        }
        ws[lane] = t;
    }
    __syncthreads();
    s += wid ? ws[wid - 1] : 0;

    if (tid == 1023)
        atomicExch(&g_lb[b], (((unsigned long long)(unsigned)s) << 1) | 1ull);
    if (tid < b) {
        unsigned long long x;
        do { x = atomicAdd(&g_lb[tid], 0ull); } while (!(x & 1ull));
        preds[tid] = (int)(x >> 1);
    }
    __syncthreads();
    if (tid == 0) {
        int acc = 0;
        for (int j = 0; j < b; j++) acc += preds[j];
        sbase = acc;
    }
    __syncthreads();
    s += sbase;

    if (i < Nn) {
        g_off[i + 1] = s;
        g_cur[i] = s - v;
    }
    if (i == 0) g_off[0] = 0;
    gbar(&g_bar[2]);

    // phase 3: CSR fill
    for (int e = b * 1024 + tid; e < E; e += gstride) {
        int d = dst[e];
        int p = atomicAdd(&g_cur[d], 1);
        g_csr[p] = src[e];
    }
}

// ---------------- segment-mean aggregation (warp per node, no smem, high occ) ----------------
__global__ void k_agg(const float* __restrict__ A, float* __restrict__ out) {
    int w = threadIdx.x >> 5, l = threadIdx.x & 31;
    int node = blockIdx.x * 8 + w;
    if (node >= Nn) return;
    int s = g_off[node], e = g_off[node + 1];
    int deg = e - s;
    float4 a0 = make_float4(0.f, 0.f, 0.f, 0.f);
    float4 a1 = make_float4(0.f, 0.f, 0.f, 0.f);
    float4 a2 = make_float4(0.f, 0.f, 0.f, 0.f);
    float4 a3 = make_float4(0.f, 0.f, 0.f, 0.f);
    for (int base = s; base < e; base += 32) {
        int cnt = e - base; if (cnt > 32) cnt = 32;
        int idx = (l < cnt) ? g_csr[base + l] : 0;
        int j = 0;
        for (; j + 4 <= cnt; j += 4) {
            int r0 = __shfl_sync(0xffffffffu, idx, j);
            int r1 = __shfl_sync(0xffffffffu, idx, j + 1);
            int r2 = __shfl_sync(0xffffffffu, idx, j + 2);
            int r3 = __shfl_sync(0xffffffffu, idx, j + 3);
            float4 v0 = ((const float4*)(A + (size_t)r0 * D))[l];
            float4 v1 = ((const float4*)(A + (size_t)r1 * D))[l];
            float4 v2 = ((const float4*)(A + (size_t)r2 * D))[l];
            float4 v3 = ((const float4*)(A + (size_t)r3 * D))[l];
            a0.x += v0.x; a0.y += v0.y; a0.z += v0.z; a0.w += v0.w;
            a1.x += v1.x; a1.y += v1.y; a1.z += v1.z; a1.w += v1.w;
            a2.x += v2.x; a2.y += v2.y; a2.z += v2.z; a2.w += v2.w;
            a3.x += v3.x; a3.y += v3.y; a3.z += v3.z; a3.w += v3.w;
        }
        for (; j < cnt; j++) {
            int r = __shfl_sync(0xffffffffu, idx, j);
            float4 vv = ((const float4*)(A + (size_t)r * D))[l];
            a0.x += vv.x; a0.y += vv.y; a0.z += vv.z; a0.w += vv.w;
        }
    }
    a0.x += a1.x + a2.x + a3.x;
    a0.y += a1.y + a2.y + a3.y;
    a0.z += a1.z + a2.z + a3.z;
    a0.w += a1.w + a2.w + a3.w;
    float inv = 1.0f / (float)(deg > 1 ? deg : 1);
    a0.x *= inv; a0.y *= inv; a0.z *= inv; a0.w *= inv;
    ((float4*)(out + (size_t)node * D))[l] = a0;
}

// ---------------- persistent dual GEMM + BN + leaky ----------------
// 96 nodes/tile, 768 threads (24 warps = 12 groups x 2 col-halves), occ 37.5%.
// smem: sWsP[16384] + sWnP[16384] + sVal[48 pairs x 512] = 57344 floats = 224KB
#define GEMM_SMEM_BYTES (57344 * 4)
__global__ void __launch_bounds__(768, 1) k_gemm(
        const float* __restrict__ A, const float* __restrict__ G,
        const float* __restrict__ Ws, const float* __restrict__ Wn,
        const float* __restrict__ bias, const float* __restrict__ gamma,
        const float* __restrict__ beta, const float* __restrict__ rm,
        const float* __restrict__ rv, float* __restrict__ out, int fixnan) {
    extern __shared__ float sm[];
    float* sWsP = sm;               // [0, 16384)
    float* sWnP = sm + 16384;       // [16384, 32768)
    float* sVal = sm + 32768;       // [32768, 57344)  pair stride 512
    for (int idx = threadIdx.x; idx < 4096; idx += 768) {
        int kp = idx >> 6;
        int cg = idx & 63;
        float2 a0 = *(const float2*)&Ws[(2 * kp) * 128 + 2 * cg];
        float2 b0 = *(const float2*)&Ws[(2 * kp + 1) * 128 + 2 * cg];
        *(float4*)&sWsP[(kp * 128 + 2 * cg) * 2] = make_float4(a0.x, b0.x, a0.y, b0.y);
        float2 a1 = *(const float2*)&Wn[(2 * kp) * 128 + 2 * cg];
        float2 b1 = *(const float2*)&Wn[(2 * kp + 1) * 128 + 2 * cg];
        *(float4*)&sWnP[(kp * 128 + 2 * cg) * 2] = make_float4(a1.x, b1.x, a1.y, b1.y);
    }
    __syncthreads();

    int w = threadIdx.x >> 5, l = threadIdx.x & 31;
    int g = w >> 1, h = w & 1;
    int c0 = 64 * h + 2 * l;
    float2 bb = *(const float2*)&bias[c0];
    float2 ga = *(const float2*)&gamma[c0];
    float2 be = *(const float2*)&beta[c0];
    float2 rmv = *(const float2*)&rm[c0];
    float2 rvv = *(const float2*)&rv[c0];
    float scl0 = ga.x * rsqrtf(rvv.x + BN_EPS), shf0 = be.x - rmv.x * scl0;
    float scl1 = ga.y * rsqrtf(rvv.y + BN_EPS), shf1 = be.y - rmv.y * scl1;

    for (int tile = blockIdx.x; tile < NT96; tile += 148) {
        int blockBase = tile * 96;
#pragma unroll
        for (int pr = 0; pr < 2; pr++) {
            int p = w * 2 + pr;
            int nA = blockBase + p * 2, nB = nA + 1;
            float4 xA = make_float4(0.f, 0.f, 0.f, 0.f), xB = xA, aA = xA, aB = xA;
            if (nA < Nn) {
                xA = ((const float4*)(A + (size_t)nA * D))[l];
                aA = ((const float4*)(G + (size_t)nA * D))[l];
            }
            if (nB < Nn) {
                xB = ((const float4*)(A + (size_t)nB * D))[l];
                aB = ((const float4*)(G + (size_t)nB * D))[l];
            }
            float* bx = sVal + p * 512;
            *(float4*)(bx + 8 * l)           = make_float4(xA.x, xA.y, xB.x, xB.y);
            *(float4*)(bx + 8 * l + 4)       = make_float4(xA.z, xA.w, xB.z, xB.w);
            *(float4*)(bx + 256 + 8 * l)     = make_float4(aA.x, aA.y, aB.x, aB.y);
            *(float4*)(bx + 256 + 8 * l + 4) = make_float4(aA.z, aA.w, aB.z, aB.w);
        }
        __syncthreads();

        const float* wsb = sWsP + 128 * h + 4 * l;
        const float* wnb = sWnP + 128 * h + 4 * l;
        const float* vb = sVal + g * 4 * 512;
        unsigned long long acc[8][2];
#pragma unroll
        for (int n = 0; n < 8; n++) { acc[n][0] = 0ull; acc[n][1] = 0ull; }
#pragma unroll 4
        for (int kp = 0; kp < 64; kp++) {
            ulonglong2 wS = *(const ulonglong2*)(wsb + kp * 256);
            ulonglong2 wN = *(const ulonglong2*)(wnb + kp * 256);
#pragma unroll
            for (int p = 0; p < 4; p++) {
                ulonglong2 vx = *(const ulonglong2*)(vb + p * 512 + kp * 4);
                ulonglong2 va = *(const ulonglong2*)(vb + p * 512 + 256 + kp * 4);
                FMA2(acc[2 * p][0], vx.x, wS.x);     FMA2(acc[2 * p][1], vx.x, wS.y);
                FMA2(acc[2 * p + 1][0], vx.y, wS.x); FMA2(acc[2 * p + 1][1], vx.y, wS.y);
                FMA2(acc[2 * p][0], va.x, wN.x);     FMA2(acc[2 * p][1], va.x, wN.y);
                FMA2(acc[2 * p + 1][0], va.y, wN.x); FMA2(acc[2 * p + 1][1], va.y, wN.y);
            }
        }

#pragma unroll
        for (int n = 0; n < 8; n++) {
            int node = blockBase + 8 * g + n;
            if (node >= Nn) continue;
            float pe, po;
            UNPACK2(pe, po, acc[n][0]);
            float v0 = (pe + po) + bb.x;
            v0 = v0 * scl0 + shf0;
            v0 = v0 >= 0.f ? v0 : NEG * v0;
            UNPACK2(pe, po, acc[n][1]);
            float v1 = (pe + po) + bb.y;
            v1 = v1 * scl1 + shf1;
            v1 = v1 >= 0.f ? v1 : NEG * v1;
            if (fixnan) {
                if (isnan(v0)) v0 = 1e-14f;
                else if (isinf(v0)) v0 = v0 > 0.f ? 3.402823466e38f : -3.402823466e38f;
                if (isnan(v1)) v1 = 1e-14f;
                else if (isinf(v1)) v1 = v1 > 0.f ? 3.402823466e38f : -3.402823466e38f;
            }
            *(float2*)&out[(size_t)node * D + c0] = make_float2(v0, v1);
        }
        __syncthreads();
    }
}

// ---------------- persistent node-level MLP layer0 projection ----------------
// 96 nodes/tile, 768 threads (24 warps x 4 nodes). smem: sWI 64KB + sVal 96KB = 160KB
#define PREP_SMEM_BYTES (40960 * 4)
__global__ void __launch_bounds__(768, 1) k_prep(
        const float* __restrict__ h, const float* __restrict__ mw0,
        float* __restrict__ pu, float* __restrict__ pv) {
    extern __shared__ float sm[];
    float* sWI = sm;            // [0, 16384)
    float* sVal = sm + 16384;   // [16384, 40960)  node stride 256
    for (int idx = threadIdx.x; idx < 4096; idx += 768) {
        int k = idx >> 5, p = idx & 31;
        float2 u = *(const float2*)&mw0[k * 64 + 2 * p];
        float2 v = *(const float2*)&mw0[(128 + k) * 64 + 2 * p];
        *(float4*)&sWI[k * 128 + p * 4] = make_float4(u.x, u.y, v.x, v.y);
    }
    __syncthreads();

    int w = threadIdx.x >> 5, l = threadIdx.x & 31;
    int nl0 = w * 4;

    for (int tile = blockIdx.x; tile < NT96; tile += 148) {
        int n0 = tile * 96 + nl0;
#pragma unroll
        for (int t = 0; t < 4; t++) {
            int node = n0 + t;
            float4 xv = make_float4(0.f, 0.f, 0.f, 0.f);
            if (node < Nn) xv = ((const float4*)(h + (size_t)node * D))[l];
            float4* sd = (float4*)(sVal + (nl0 + t) * 256 + l * 8);
            sd[0] = make_float4(xv.x, xv.x, xv.y, xv.y);
            sd[1] = make_float4(xv.z, xv.z, xv.w, xv.w);
        }
        __syncwarp();

        unsigned long long au[4] = {0ull, 0ull, 0ull, 0ull};
        unsigned long long av[4] = {0ull, 0ull, 0ull, 0ull};
        const float* wib = sWI + l * 4;
        const float* vb = sVal + nl0 * 256;
#pragma unroll 8
        for (int k = 0; k < 128; k++) {
            ulonglong2 wp = *(const ulonglong2*)(wib + k * 128);
#pragma unroll
            for (int t = 0; t < 4; t++) {
                unsigned long long xd = *(const unsigned long long*)(vb + t * 256 + 2 * k);
                FMA2(au[t], xd, wp.x);
                FMA2(av[t], xd, wp.y);
            }
        }
#pragma unroll
        for (int t = 0; t < 4; t++) {
            int node = n0 + t;
            if (node >= Nn) continue;
            *(float2*)&pu[(size_t)node * 64 + 2 * l] = *(float2*)&au[t];
            *(float2*)&pv[(size_t)node * 64 + 2 * l] = *(float2*)&av[t];
        }
        __syncwarp();
    }
}

// ---------------- candidate kernel ----------------
#define Z0STRIDE 136
#define CAND_SMEM_FLOATS 13060
__global__ void k_cand(const float* __restrict__ pu, const float* __restrict__ pv,
                       const int* __restrict__ cu, const int* __restrict__ cv,
                       const float* __restrict__ cf,
                       const float* __restrict__ mw0, const float* __restrict__ mb0,
                       const float* __restrict__ mw1, const float* __restrict__ mb1,
                       const float* __restrict__ mw2, const float* __restrict__ mb2,
                       float* __restrict__ y, int C) {
    extern __shared__ float smc[];
    float* w1s = smc;
    float* z0sD = smc + 4096;
    float* wfs = smc + 12800;
    float* b0s = smc + 12864;
    float* b1s = smc + 12928;
    float* w2s = smc + 12992;
    float* b2s = smc + 13056;
    int tid = threadIdx.x;
    for (int i = tid; i < 4096; i += 256) w1s[i] = mw1[i];
    if (tid < 64) {
        wfs[tid] = mw0[256 * 64 + tid];
        b0s[tid] = mb0[tid];
        b1s[tid] = mb1[tid];
        w2s[tid] = mw2[tid];
    }
    if (tid == 0) b2s[0] = mb2[0];
    __syncthreads();

    int base = blockIdx.x * 64;

    {
        int jc = tid & 15, j = jc * 4;
        int c0 = tid >> 4;
#pragma unroll
        for (int i = 0; i < 4; i++) {
            int cl = c0 + 16 * i;
            int gc = base + cl;
            float4 z = make_float4(0.f, 0.f, 0.f, 0.f);
            if (gc < C) {
                int u = cu[gc], v = cv[gc];
                float f = cf[gc];
                float4 a = *(const float4*)&pu[(size_t)u * 64 + j];
                float4 b = *(const float4*)&pv[(size_t)v * 64 + j];
                float4 wf4 = *(const float4*)&wfs[j];
                float4 bb4 = *(const float4*)&b0s[j];
                z.x = a.x + b.x + f * wf4.x + bb4.x;
                z.y = a.y + b.y + f * wf4.y + bb4.y;
                z.z = a.z + b.z + f * wf4.z + bb4.z;
                z.w = a.w + b.w + f * wf4.w + bb4.w;
                z.x = z.x >= 0.f ? z.x : NEG * z.x;
                z.y = z.y >= 0.f ? z.y : NEG * z.y;
                z.z = z.z >= 0.f ? z.z : NEG * z.z;
                z.w = z.w >= 0.f ? z.w : NEG * z.w;
            }
            float* zd = &z0sD[cl * Z0STRIDE + 2 * j];
            ((float4*)zd)[0] = make_float4(z.x, z.x, z.y, z.y);
            ((float4*)zd)[1] = make_float4(z.z, z.z, z.w, z.w);
        }
    }
    __syncthreads();

    {
        int oc = tid & 15, cg = tid >> 4;
        int ob = oc * 4;
        unsigned long long a01[4] = {0ull, 0ull, 0ull, 0ull};
        unsigned long long a23[4] = {0ull, 0ull, 0ull, 0ull};
        const float* z0 = &z0sD[(cg * 4 + 0) * Z0STRIDE];
        const float* z1 = &z0sD[(cg * 4 + 1) * Z0STRIDE];
        const float* z2 = &z0sD[(cg * 4 + 2) * Z0STRIDE];
        const float* z3 = &z0sD[(cg * 4 + 3) * Z0STRIDE];
#pragma unroll 8
        for (int k = 0; k < 64; k++) {
            ulonglong2 wp = *(const ulonglong2*)&w1s[k * 64 + ob];
            unsigned long long q0 = *(const unsigned long long*)(z0 + 2 * k);
            unsigned long long q1 = *(const unsigned long long*)(z1 + 2 * k);
            unsigned long long q2 = *(const unsigned long long*)(z2 + 2 * k);
            unsigned long long q3 = *(const unsigned long long*)(z3 + 2 * k);
            FMA2(a01[0], q0, wp.x); FMA2(a23[0], q0, wp.y);
            FMA2(a01[1], q1, wp.x); FMA2(a23[1], q1, wp.y);
            FMA2(a01[2], q2, wp.x); FMA2(a23[2], q2, wp.y);
            FMA2(a01[3], q3, wp.x); FMA2(a23[3], q3, wp.y);
        }
        float4 bb = *(const float4*)&b1s[ob];
        float4 w2v = *(const float4*)&w2s[ob];
        float part[4];
#pragma unroll
        for (int q = 0; q < 4; q++) {
            float t0, t1, t2, t3;
            UNPACK2(t0, t1, a01[q]);
            UNPACK2(t2, t3, a23[q]);
            t0 += bb.x; t0 = t0 >= 0.f ? t0 : NEG * t0;
            t1 += bb.y; t1 = t1 >= 0.f ? t1 : NEG * t1;
            t2 += bb.z; t2 = t2 >= 0.f ? t2 : NEG * t2;
            t3 += bb.w; t3 = t3 >= 0.f ? t3 : NEG * t3;
            part[q] = t0 * w2v.x + t1 * w2v.y + t2 * w2v.z + t3 * w2v.w;
        }
#pragma unroll
        for (int q = 0; q < 4; q++) {
#pragma unroll
            for (int o = 8; o; o >>= 1)
                part[q] += __shfl_xor_sync(0xffffffffu, part[q], o);
        }
        if (oc == 0) {
#pragma unroll
            for (int q = 0; q < 4; q++) {
                int gc = base + cg * 4 + q;
                if (gc < C) y[gc] = part[q] + b2s[0];
            }
        }
    }
}

// ---------------- softmax (2 kernels, deterministic) ----------------
__global__ void k_softA(const float* __restrict__ y, int C) {
    __shared__ float mm[256], ss[256];
    float m = -3.402823466e38f, s = 0.f;
    for (int i = blockIdx.x * 256 + threadIdx.x; i < C; i += gridDim.x * 256) {
        float v = y[i];
        if (v > m) { s = s * expf(m - v) + 1.0f; m = v; }
        else s += expf(v - m);
    }
    mm[threadIdx.x] = m; ss[threadIdx.x] = s;
    __syncthreads();
    for (int st = 128; st; st >>= 1) {
        if (threadIdx.x < st) {
            float m2 = mm[threadIdx.x + st], s2 = ss[threadIdx.x + st];
            float M = fmaxf(mm[threadIdx.x], m2);
            ss[threadIdx.x] = ss[threadIdx.x] * expf(mm[threadIdx.x] - M) + s2 * expf(m2 - M);
            mm[threadIdx.x] = M;
        }
        __syncthreads();
    }
    if (threadIdx.x == 0) { g_part[blockIdx.x] = mm[0]; g_part[128 + blockIdx.x] = ss[0]; }
}

__global__ void k_softFin(const float* __restrict__ y, float* __restrict__ out, int C) {
    __shared__ float mm[128], ss[128];
    int t = threadIdx.x;
    if (t < 128) { mm[t] = g_part[t]; ss[t] = g_part[128 + t]; }
    __syncthreads();
    for (int st = 64; st; st >>= 1) {
        if (t < st) {
            float m2 = mm[t + st], s2 = ss[t + st];
            float M = fmaxf(mm[t], m2);
            ss[t] = ss[t] * expf(mm[t] - M) + s2 * expf(m2 - M);
            mm[t] = M;
        }
        __syncthreads();
    }
    float mx = mm[0];
    float inv = 1.0f / ss[0];
    for (int i = blockIdx.x * 256 + t; i < C; i += gridDim.x * 256)
        out[i] = expf(y[i] - mx) * inv;
}

// ---------------- host launcher ----------------
extern "C" void kernel_launch(void* const* d_in, const int* in_sizes, int n_in,
                              void* d_out, int out_size) {
    const float* x   = (const float*)d_in[0];
    const int* src   = (const int*)d_in[1];
    const int* dst   = (const int*)d_in[2];
    const int* cu    = (const int*)d_in[3];
    const int* cv    = (const int*)d_in[4];
    const float* cf  = (const float*)d_in[5];
    const float* ws0 = (const float*)d_in[6];
    const float* wn0 = (const float*)d_in[7];
    const float* b0  = (const float*)d_in[8];
    const float* ga0 = (const float*)d_in[9];
    const float* be0 = (const float*)d_in[10];
    const float* rm0 = (const float*)d_in[11];
    const float* rv0 = (const float*)d_in[12];
    const float* ws1 = (const float*)d_in[13];
    const float* wn1 = (const float*)d_in[14];
    const float* b1  = (const float*)d_in[15];
    const float* ga1 = (const float*)d_in[16];
    const float* be1 = (const float*)d_in[17];
    const float* rm1 = (const float*)d_in[18];
    const float* rv1 = (const float*)d_in[19];
    const float* mw0 = (const float*)d_in[20];
    const float* mb0 = (const float*)d_in[21];
    const float* mw1 = (const float*)d_in[22];
    const float* mb1 = (const float*)d_in[23];
    const float* mw2 = (const float*)d_in[24];
    const float* mb2 = (const float*)d_in[25];

    int E = in_sizes[1];
    int C = in_sizes[3];
    float* y = (float*)d_out;
    float* soft = y + C;

    float *h0p, *h1p, *aggp, *pup, *pvp;
    cudaGetSymbolAddress((void**)&h0p, g_h0);
    cudaGetSymbolAddress((void**)&h1p, g_h1);
    cudaGetSymbolAddress((void**)&aggp, g_agg);
    cudaGetSymbolAddress((void**)&pup, g_pu);
    cudaGetSymbolAddress((void**)&pvp, g_pv);

    cudaFuncSetAttribute(k_gemm, cudaFuncAttributeMaxDynamicSharedMemorySize, GEMM_SMEM_BYTES);
    cudaFuncSetAttribute(k_prep, cudaFuncAttributeMaxDynamicSharedMemorySize, PREP_SMEM_BYTES);
    cudaFuncSetAttribute(k_cand, cudaFuncAttributeMaxDynamicSharedMemorySize, CAND_SMEM_FLOATS * 4);

    // 1: reset barrier/lookback state
    k_zero<<<1, 256>>>();
    // 2: zero-deg + count + scan + fill (merged, 148 co-resident blocks)
    k_csr<<<NB_CSR, 1024>>>(src, dst, E);
    // 3: agg layer 0
    k_agg<<<(Nn + 7) / 8, 256>>>(x, aggp);
    // 4: gemm layer 0 (PROFILED SLOT)
    k_gemm<<<148, 768, GEMM_SMEM_BYTES>>>(x, aggp, ws0, wn0, b0, ga0, be0, rm0, rv0, h0p, 0);
    // 5: agg layer 1
    k_agg<<<(Nn + 7) / 8, 256>>>(h0p, aggp);
    // 6: gemm layer 1 (+ nan_to_num)
    k_gemm<<<148, 768, GEMM_SMEM_BYTES>>>(h0p, aggp, ws1, wn1, b1, ga1, be1, rm1, rv1, h1p, 1);
    // 7: MLP layer0 hoisted to node level (persistent)
    k_prep<<<148, 768, PREP_SMEM_BYTES>>>(h1p, mw0, pup, pvp);
    // 8: candidate tail -> y
    k_cand<<<(C + 63) / 64, 256, CAND_SMEM_FLOATS * 4>>>(pup, pvp, cu, cv, cf, mw0, mb0, mw1, mb1, mw2, mb2, y, C);
    // 9,10: softmax
    k_softA<<<128, 256>>>(y, C);
    k_softFin<<<256, 256>>>(y, soft, C);
}

// round 16
// speedup vs baseline: 1.1334x; 1.0363x over previous
#include <cuda_runtime.h>
#include <cuda_bf16.h>
#include <mma.h>
#include <math.h>

using namespace nvcuda;

#define Nn 50000
#define Ee 800000
#define Cc 100000
#define D 128
#define NEG 0.01f
#define BN_EPS 1e-5f
#define NB_CSR 148
#define NT96 ((Nn + 95) / 96)
#define NT64 ((Nn + 63) / 64)

#define FMA2(d, a, b) asm("fma.rn.f32x2 %0, %1, %2, %0;" : "+l"(d) : "l"(a), "l"(b))
#define UNPACK2(lo, hi, v) asm("mov.b64 {%0, %1}, %2;" : "=f"(lo), "=f"(hi) : "l"(v))

// ---------------- scratch (static __device__, no allocation) ----------------
__device__ float g_h0[(size_t)Nn * D];
__device__ float g_h1[(size_t)Nn * D];
__device__ float g_agg[(size_t)Nn * D];
__device__ float g_pu[(size_t)Nn * 64];
__device__ float g_pv[(size_t)Nn * 64];
__device__ int   g_deg[Nn];
__device__ int   g_off[Nn + 1];
__device__ int   g_cur[Nn];
__device__ int   g_csr[Ee];
__device__ unsigned long long g_lb[NB_CSR];
__device__ unsigned int g_bar[8];
__device__ float g_part[256];

// ---------------- tiny reset ----------------
__global__ void k_zero() {
    int i = threadIdx.x;
    if (i < NB_CSR) g_lb[i] = 0ull;
    if (i < 8) g_bar[i] = 0u;
}

// ---------------- merged: zero-deg + count + scan + fill ----------------
__device__ __forceinline__ void gbar(unsigned int* ctr) {
    __threadfence();
    __syncthreads();
    if (threadIdx.x == 0) {
        atomicAdd(ctr, 1u);
        while (atomicAdd(ctr, 0u) < (unsigned)NB_CSR) {}
    }
    __syncthreads();
}

__global__ void k_csr(const int* __restrict__ src, const int* __restrict__ dst, int E) {
    __shared__ int ws[32];
    __shared__ int preds[NB_CSR];
    __shared__ int sbase;
    int b = blockIdx.x;
    int tid = threadIdx.x;
    int lane = tid & 31, wid = tid >> 5;
    int gstride = NB_CSR * 1024;

    for (int i = b * 1024 + tid; i < Nn; i += gstride) g_deg[i] = 0;
    gbar(&g_bar[0]);

    for (int e = b * 1024 + tid; e < E; e += gstride)
        atomicAdd(&g_deg[dst[e]], 1);
    gbar(&g_bar[1]);

    int i = b * 1024 + tid;
    int v = (i < Nn) ? g_deg[i] : 0;
    int s = v;
#pragma unroll
    for (int o = 1; o < 32; o <<= 1) {
        int t = __shfl_up_sync(0xffffffffu, s, o);
        if (lane >= o) s += t;
    }
    if (lane == 31) ws[wid] = s;
    __syncthreads();
    if (wid == 0) {
        int t = ws[lane];
#pragma unroll
        for (int o = 1; o < 32; o <<= 1) {
            int u = __shfl_up_sync(0xffffffffu, t, o);
            if (lane >= o) t += u;
        }
        ws[lane] = t;
    }
    __syncthreads();
    s += wid ? ws[wid - 1] : 0;

    if (tid == 1023)
        atomicExch(&g_lb[b], (((unsigned long long)(unsigned)s) << 1) | 1ull);
    if (tid < b) {
        unsigned long long x;
        do { x = atomicAdd(&g_lb[tid], 0ull); } while (!(x & 1ull));
        preds[tid] = (int)(x >> 1);
    }
    __syncthreads();
    if (tid == 0) {
        int acc = 0;
        for (int j = 0; j < b; j++) acc += preds[j];
        sbase = acc;
    }
    __syncthreads();
    s += sbase;

    if (i < Nn) {
        g_off[i + 1] = s;
        g_cur[i] = s - v;
    }
    if (i == 0) g_off[0] = 0;
    gbar(&g_bar[2]);

    for (int e = b * 1024 + tid; e < E; e += gstride) {
        int d = dst[e];
        int p = atomicAdd(&g_cur[d], 1);
        g_csr[p] = src[e];
    }
}

// ---------------- segment-mean aggregation ----------------
__global__ void k_agg(const float* __restrict__ A, float* __restrict__ out) {
    int w = threadIdx.x >> 5, l = threadIdx.x & 31;
    int node = blockIdx.x * 8 + w;
    if (node >= Nn) return;
    int s = g_off[node], e = g_off[node + 1];
    int deg = e - s;
    float4 a0 = make_float4(0.f, 0.f, 0.f, 0.f);
    float4 a1 = make_float4(0.f, 0.f, 0.f, 0.f);
    float4 a2 = make_float4(0.f, 0.f, 0.f, 0.f);
    float4 a3 = make_float4(0.f, 0.f, 0.f, 0.f);
    for (int base = s; base < e; base += 32) {
        int cnt = e - base; if (cnt > 32) cnt = 32;
        int idx = (l < cnt) ? g_csr[base + l] : 0;
        int j = 0;
        for (; j + 4 <= cnt; j += 4) {
            int r0 = __shfl_sync(0xffffffffu, idx, j);
            int r1 = __shfl_sync(0xffffffffu, idx, j + 1);
            int r2 = __shfl_sync(0xffffffffu, idx, j + 2);
            int r3 = __shfl_sync(0xffffffffu, idx, j + 3);
            float4 v0 = ((const float4*)(A + (size_t)r0 * D))[l];
            float4 v1 = ((const float4*)(A + (size_t)r1 * D))[l];
            float4 v2 = ((const float4*)(A + (size_t)r2 * D))[l];
            float4 v3 = ((const float4*)(A + (size_t)r3 * D))[l];
            a0.x += v0.x; a0.y += v0.y; a0.z += v0.z; a0.w += v0.w;
            a1.x += v1.x; a1.y += v1.y; a1.z += v1.z; a1.w += v1.w;
            a2.x += v2.x; a2.y += v2.y; a2.z += v2.z; a2.w += v2.w;
            a3.x += v3.x; a3.y += v3.y; a3.z += v3.z; a3.w += v3.w;
        }
        for (; j < cnt; j++) {
            int r = __shfl_sync(0xffffffffu, idx, j);
            float4 vv = ((const float4*)(A + (size_t)r * D))[l];
            a0.x += vv.x; a0.y += vv.y; a0.z += vv.z; a0.w += vv.w;
        }
    }
    a0.x += a1.x + a2.x + a3.x;
    a0.y += a1.y + a2.y + a3.y;
    a0.z += a1.z + a2.z + a3.z;
    a0.w += a1.w + a2.w + a3.w;
    float inv = 1.0f / (float)(deg > 1 ? deg : 1);
    a0.x *= inv; a0.y *= inv; a0.z *= inv; a0.w *= inv;
    ((float4*)(out + (size_t)node * D))[l] = a0;
}

// ================= WMMA bf16-split GEMM =================
// h = X@Ws + G@Wn. Persistent, 64-node tiles, 512 threads (16 warps x 16x32 output).
// smem byte layout:
//   WsHi[0,34816) WsLo[34816,69632) WnHi[69632,104448) WnLo[104448,139264)
//   Ahi[139264,156672) Alo[156672,174080)   (fp32 Out reuses [139264,172032))
//   pscl[174080,174592) pshf[174592,175104)
#define WB_WSHI 0
#define WB_WSLO 34816
#define WB_WNHI 69632
#define WB_WNLO 104448
#define WB_A_HI 139264
#define WB_A_LO 156672
#define WB_OUT  139264
#define WB_PSCL 174080
#define WB_PSHF 174592
#define WMMA_SMEM 175104
#define LDA 136

__global__ void __launch_bounds__(512, 1) k_gemm(
        const float* __restrict__ Xf, const float* __restrict__ G,
        const float* __restrict__ Ws, const float* __restrict__ Wn,
        const float* __restrict__ bias, const float* __restrict__ gamma,
        const float* __restrict__ beta, const float* __restrict__ rm,
        const float* __restrict__ rv, float* __restrict__ out, int fixnan) {
    extern __shared__ char smb[];
    int tid = threadIdx.x;
    int w = tid >> 5;

    // stage weights once: bf16 hi/lo, row-major [k][n] with ld=136
    for (int m = 0; m < 2; m++) {
        const float* W = m ? Wn : Ws;
        __nv_bfloat16* bh = (__nv_bfloat16*)(smb + (m ? WB_WNHI : WB_WSHI));
        __nv_bfloat16* bl = (__nv_bfloat16*)(smb + (m ? WB_WNLO : WB_WSLO));
        for (int idx = tid; idx < 16384; idx += 512) {
            int k = idx >> 7, n = idx & 127;
            float v = W[idx];
            __nv_bfloat16 h = __float2bfloat16(v);
            bh[k * LDA + n] = h;
            bl[k * LDA + n] = __float2bfloat16(v - __bfloat162float(h));
        }
    }
    float* pscl = (float*)(smb + WB_PSCL);
    float* pshf = (float*)(smb + WB_PSHF);
    if (tid < 128) {
        float sclv = gamma[tid] * rsqrtf(rv[tid] + BN_EPS);
        pscl[tid] = sclv;
        pshf[tid] = beta[tid] - rm[tid] * sclv + bias[tid] * sclv;
    }
    __syncthreads();

    int wrow = w >> 2;      // 0..3  rows 16*wrow
    int wcol = w & 3;       // 0..3  cols 32*wcol
    __nv_bfloat16* sAh = (__nv_bfloat16*)(smb + WB_A_HI);
    __nv_bfloat16* sAl = (__nv_bfloat16*)(smb + WB_A_LO);
    float* sOut = (float*)(smb + WB_OUT);

    for (int tile = blockIdx.x; tile < NT64; tile += 148) {
        int tb = tile * 64;
        wmma::fragment<wmma::accumulator, 16, 16, 16, float> acc[2];
        wmma::fill_fragment(acc[0], 0.f);
        wmma::fill_fragment(acc[1], 0.f);

        for (int op = 0; op < 2; op++) {
            const float* S = op ? G : Xf;
            __syncthreads();  // prior readers of A/Out region done
            for (int idx = tid; idx < 2048; idx += 512) {
                int node = idx >> 5, f4 = idx & 31;
                int gn = tb + node;
                float4 v = make_float4(0.f, 0.f, 0.f, 0.f);
                if (gn < Nn) v = ((const float4*)(S + (size_t)gn * D))[f4];
                __nv_bfloat16 h0 = __float2bfloat16(v.x);
                __nv_bfloat16 h1 = __float2bfloat16(v.y);
                __nv_bfloat16 h2 = __float2bfloat16(v.z);
                __nv_bfloat16 h3 = __float2bfloat16(v.w);
                uint2 ph, pl;
                ph.x = (unsigned)__bfloat16_as_ushort(h0) | ((unsigned)__bfloat16_as_ushort(h1) << 16);
                ph.y = (unsigned)__bfloat16_as_ushort(h2) | ((unsigned)__bfloat16_as_ushort(h3) << 16);
                __nv_bfloat16 e0 = __float2bfloat16(v.x - __bfloat162float(h0));
                __nv_bfloat16 e1 = __float2bfloat16(v.y - __bfloat162float(h1));
                __nv_bfloat16 e2 = __float2bfloat16(v.z - __bfloat162float(h2));
                __nv_bfloat16 e3 = __float2bfloat16(v.w - __bfloat162float(h3));
                pl.x = (unsigned)__bfloat16_as_ushort(e0) | ((unsigned)__bfloat16_as_ushort(e1) << 16);
                pl.y = (unsigned)__bfloat16_as_ushort(e2) | ((unsigned)__bfloat16_as_ushort(e3) << 16);
                *(uint2*)&sAh[node * LDA + f4 * 4] = ph;
                *(uint2*)&sAl[node * LDA + f4 * 4] = pl;
            }
            __syncthreads();

            const __nv_bfloat16* Wh = (const __nv_bfloat16*)(smb + (op ? WB_WNHI : WB_WSHI));
            const __nv_bfloat16* Wl = (const __nv_bfloat16*)(smb + (op ? WB_WNLO : WB_WSLO));
#pragma unroll
            for (int sp = 0; sp < 3; sp++) {
                const __nv_bfloat16* Ap = (sp == 2) ? sAl : sAh;
                const __nv_bfloat16* Wp = (sp == 1) ? Wl : Wh;
#pragma unroll
                for (int k = 0; k < 8; k++) {
                    wmma::fragment<wmma::matrix_a, 16, 16, 16, __nv_bfloat16, wmma::row_major> af;
                    wmma::load_matrix_sync(af, Ap + (wrow * 16) * LDA + k * 16, LDA);
#pragma unroll
                    for (int c = 0; c < 2; c++) {
                        wmma::fragment<wmma::matrix_b, 16, 16, 16, __nv_bfloat16, wmma::row_major> bf;
                        wmma::load_matrix_sync(bf, Wp + (k * 16) * LDA + wcol * 32 + c * 16, LDA);
                        wmma::mma_sync(acc[c], af, bf, acc[c]);
                    }
                }
            }
        }
        __syncthreads();  // all mma A-reads done before Out overwrites A region
        wmma::store_matrix_sync(sOut + (wrow * 16) * 128 + wcol * 32, acc[0], 128, wmma::mem_row_major);
        wmma::store_matrix_sync(sOut + (wrow * 16) * 128 + wcol * 32 + 16, acc[1], 128, wmma::mem_row_major);
        __syncthreads();

        for (int idx = tid; idx < 2048; idx += 512) {
            int node = idx >> 5, f4 = idx & 31;
            int gn = tb + node;
            if (gn >= Nn) continue;
            float4 dv = *(float4*)&sOut[node * 128 + f4 * 4];
            int cb = f4 * 4;
            float4 o;
            o.x = dv.x * pscl[cb + 0] + pshf[cb + 0];
            o.y = dv.y * pscl[cb + 1] + pshf[cb + 1];
            o.z = dv.z * pscl[cb + 2] + pshf[cb + 2];
            o.w = dv.w * pscl[cb + 3] + pshf[cb + 3];
            o.x = o.x >= 0.f ? o.x : NEG * o.x;
            o.y = o.y >= 0.f ? o.y : NEG * o.y;
            o.z = o.z >= 0.f ? o.z : NEG * o.z;
            o.w = o.w >= 0.f ? o.w : NEG * o.w;
            if (fixnan) {
                if (isnan(o.x)) o.x = 1e-14f; else if (isinf(o.x)) o.x = o.x > 0.f ? 3.402823466e38f : -3.402823466e38f;
                if (isnan(o.y)) o.y = 1e-14f; else if (isinf(o.y)) o.y = o.y > 0.f ? 3.402823466e38f : -3.402823466e38f;
                if (isnan(o.z)) o.z = 1e-14f; else if (isinf(o.z)) o.z = o.z > 0.f ? 3.402823466e38f : -3.402823466e38f;
                if (isnan(o.w)) o.w = 1e-14f; else if (isinf(o.w)) o.w = o.w > 0.f ? 3.402823466e38f : -3.402823466e38f;
            }
            *(float4*)&out[(size_t)gn * D + cb] = o;
        }
    }
}

// ---------------- persistent node-level MLP layer0 projection (f32x2) ----------------
#define PREP_SMEM_BYTES (40960 * 4)
__global__ void __launch_bounds__(768, 1) k_prep(
        const float* __restrict__ h, const float* __restrict__ mw0,
        float* __restrict__ pu, float* __restrict__ pv) {
    extern __shared__ float sm[];
    float* sWI = sm;            // [0, 16384)
    float* sVal = sm + 16384;   // [16384, 40960)  node stride 256
    for (int idx = threadIdx.x; idx < 4096; idx += 768) {
        int k = idx >> 5, p = idx & 31;
        float2 u = *(const float2*)&mw0[k * 64 + 2 * p];
        float2 v = *(const float2*)&mw0[(128 + k) * 64 + 2 * p];
        *(float4*)&sWI[k * 128 + p * 4] = make_float4(u.x, u.y, v.x, v.y);
    }
    __syncthreads();

    int w = threadIdx.x >> 5, l = threadIdx.x & 31;
    int nl0 = w * 4;

    for (int tile = blockIdx.x; tile < NT96; tile += 148) {
        int n0 = tile * 96 + nl0;
#pragma unroll
        for (int t = 0; t < 4; t++) {
            int node = n0 + t;
            float4 xv = make_float4(0.f, 0.f, 0.f, 0.f);
            if (node < Nn) xv = ((const float4*)(h + (size_t)node * D))[l];
            float4* sd = (float4*)(sVal + (nl0 + t) * 256 + l * 8);
            sd[0] = make_float4(xv.x, xv.x, xv.y, xv.y);
            sd[1] = make_float4(xv.z, xv.z, xv.w, xv.w);
        }
        __syncwarp();

        unsigned long long au[4] = {0ull, 0ull, 0ull, 0ull};
        unsigned long long av[4] = {0ull, 0ull, 0ull, 0ull};
        const float* wib = sWI + l * 4;
        const float* vb = sVal + nl0 * 256;
#pragma unroll 8
        for (int k = 0; k < 128; k++) {
            ulonglong2 wp = *(const ulonglong2*)(wib + k * 128);
#pragma unroll
            for (int t = 0; t < 4; t++) {
                unsigned long long xd = *(const unsigned long long*)(vb + t * 256 + 2 * k);
                FMA2(au[t], xd, wp.x);
                FMA2(av[t], xd, wp.y);
            }
        }
#pragma unroll
        for (int t = 0; t < 4; t++) {
            int node = n0 + t;
            if (node >= Nn) continue;
            *(float2*)&pu[(size_t)node * 64 + 2 * l] = *(float2*)&au[t];
            *(float2*)&pv[(size_t)node * 64 + 2 * l] = *(float2*)&av[t];
        }
        __syncwarp();
    }
}

// ---------------- candidate kernel ----------------
#define Z0STRIDE 136
#define CAND_SMEM_FLOATS 13060
__global__ void k_cand(const float* __restrict__ pu, const float* __restrict__ pv,
                       const int* __restrict__ cu, const int* __restrict__ cv,
                       const float* __restrict__ cf,
                       const float* __restrict__ mw0, const float* __restrict__ mb0,
                       const float* __restrict__ mw1, const float* __restrict__ mb1,
                       const float* __restrict__ mw2, const float* __restrict__ mb2,
                       float* __restrict__ y, int C) {
    extern __shared__ float smc[];
    float* w1s = smc;
    float* z0sD = smc + 4096;
    float* wfs = smc + 12800;
    float* b0s = smc + 12864;
    float* b1s = smc + 12928;
    float* w2s = smc + 12992;
    float* b2s = smc + 13056;
    int tid = threadIdx.x;
    for (int i = tid; i < 4096; i += 256) w1s[i] = mw1[i];
    if (tid < 64) {
        wfs[tid] = mw0[256 * 64 + tid];
        b0s[tid] = mb0[tid];
        b1s[tid] = mb1[tid];
        w2s[tid] = mw2[tid];
    }
    if (tid == 0) b2s[0] = mb2[0];
    __syncthreads();

    int base = blockIdx.x * 64;

    {
        int jc = tid & 15, j = jc * 4;
        int c0 = tid >> 4;
#pragma unroll
        for (int i = 0; i < 4; i++) {
            int cl = c0 + 16 * i;
            int gc = base + cl;
            float4 z = make_float4(0.f, 0.f, 0.f, 0.f);
            if (gc < C) {
                int u = cu[gc], v = cv[gc];
                float f = cf[gc];
                float4 a = *(const float4*)&pu[(size_t)u * 64 + j];
                float4 b = *(const float4*)&pv[(size_t)v * 64 + j];
                float4 wf4 = *(const float4*)&wfs[j];
                float4 bb4 = *(const float4*)&b0s[j];
                z.x = a.x + b.x + f * wf4.x + bb4.x;
                z.y = a.y + b.y + f * wf4.y + bb4.y;
                z.z = a.z + b.z + f * wf4.z + bb4.z;
                z.w = a.w + b.w + f * wf4.w + bb4.w;
                z.x = z.x >= 0.f ? z.x : NEG * z.x;
                z.y = z.y >= 0.f ? z.y : NEG * z.y;
                z.z = z.z >= 0.f ? z.z : NEG * z.z;
                z.w = z.w >= 0.f ? z.w : NEG * z.w;
            }
            float* zd = &z0sD[cl * Z0STRIDE + 2 * j];
            ((float4*)zd)[0] = make_float4(z.x, z.x, z.y, z.y);
            ((float4*)zd)[1] = make_float4(z.z, z.z, z.w, z.w);
        }
    }
    __syncthreads();

    {
        int oc = tid & 15, cg = tid >> 4;
        int ob = oc * 4;
        unsigned long long a01[4] = {0ull, 0ull, 0ull, 0ull};
        unsigned long long a23[4] = {0ull, 0ull, 0ull, 0ull};
        const float* z0 = &z0sD[(cg * 4 + 0) * Z0STRIDE];
        const float* z1 = &z0sD[(cg * 4 + 1) * Z0STRIDE];
        const float* z2 = &z0sD[(cg * 4 + 2) * Z0STRIDE];
        const float* z3 = &z0sD[(cg * 4 + 3) * Z0STRIDE];
#pragma unroll 8
        for (int k = 0; k < 64; k++) {
            ulonglong2 wp = *(const ulonglong2*)&w1s[k * 64 + ob];
            unsigned long long q0 = *(const unsigned long long*)(z0 + 2 * k);
            unsigned long long q1 = *(const unsigned long long*)(z1 + 2 * k);
            unsigned long long q2 = *(const unsigned long long*)(z2 + 2 * k);
            unsigned long long q3 = *(const unsigned long long*)(z3 + 2 * k);
            FMA2(a01[0], q0, wp.x); FMA2(a23[0], q0, wp.y);
            FMA2(a01[1], q1, wp.x); FMA2(a23[1], q1, wp.y);
            FMA2(a01[2], q2, wp.x); FMA2(a23[2], q2, wp.y);
            FMA2(a01[3], q3, wp.x); FMA2(a23[3], q3, wp.y);
        }
        float4 bb = *(const float4*)&b1s[ob];
        float4 w2v = *(const float4*)&w2s[ob];
        float part[4];
#pragma unroll
        for (int q = 0; q < 4; q++) {
            float t0, t1, t2, t3;
            UNPACK2(t0, t1, a01[q]);
            UNPACK2(t2, t3, a23[q]);
            t0 += bb.x; t0 = t0 >= 0.f ? t0 : NEG * t0;
            t1 += bb.y; t1 = t1 >= 0.f ? t1 : NEG * t1;
            t2 += bb.z; t2 = t2 >= 0.f ? t2 : NEG * t2;
            t3 += bb.w; t3 = t3 >= 0.f ? t3 : NEG * t3;
            part[q] = t0 * w2v.x + t1 * w2v.y + t2 * w2v.z + t3 * w2v.w;
        }
#pragma unroll
        for (int q = 0; q < 4; q++) {
#pragma unroll
            for (int o = 8; o; o >>= 1)
                part[q] += __shfl_xor_sync(0xffffffffu, part[q], o);
        }
        if (oc == 0) {
#pragma unroll
            for (int q = 0; q < 4; q++) {
                int gc = base + cg * 4 + q;
                if (gc < C) y[gc] = part[q] + b2s[0];
            }
        }
    }
}

// ---------------- softmax (2 kernels, deterministic) ----------------
__global__ void k_softA(const float* __restrict__ y, int C) {
    __shared__ float mm[256], ss[256];
    float m = -3.402823466e38f, s = 0.f;
    for (int i = blockIdx.x * 256 + threadIdx.x; i < C; i += gridDim.x * 256) {
        float v = y[i];
        if (v > m) { s = s * expf(m - v) + 1.0f; m = v; }
        else s += expf(v - m);
    }
    mm[threadIdx.x] = m; ss[threadIdx.x] = s;
    __syncthreads();
    for (int st = 128; st; st >>= 1) {
        if (threadIdx.x < st) {
            float m2 = mm[threadIdx.x + st], s2 = ss[threadIdx.x + st];
            float M = fmaxf(mm[threadIdx.x], m2);
            ss[threadIdx.x] = ss[threadIdx.x] * expf(mm[threadIdx.x] - M) + s2 * expf(m2 - M);
            mm[threadIdx.x] = M;
        }
        __syncthreads();
    }
    if (threadIdx.x == 0) { g_part[blockIdx.x] = mm[0]; g_part[128 + blockIdx.x] = ss[0]; }
}

__global__ void k_softFin(const float* __restrict__ y, float* __restrict__ out, int C) {
    __shared__ float mm[128], ss[128];
    int t = threadIdx.x;
    if (t < 128) { mm[t] = g_part[t]; ss[t] = g_part[128 + t]; }
    __syncthreads();
    for (int st = 64; st; st >>= 1) {
        if (t < st) {
            float m2 = mm[t + st], s2 = ss[t + st];
            float M = fmaxf(mm[t], m2);
            ss[t] = ss[t] * expf(mm[t] - M) + s2 * expf(m2 - M);
            mm[t] = M;
        }
        __syncthreads();
    }
    float mx = mm[0];
    float inv = 1.0f / ss[0];
    for (int i = blockIdx.x * 256 + t; i < C; i += gridDim.x * 256)
        out[i] = expf(y[i] - mx) * inv;
}

// ---------------- host launcher ----------------
extern "C" void kernel_launch(void* const* d_in, const int* in_sizes, int n_in,
                              void* d_out, int out_size) {
    const float* x   = (const float*)d_in[0];
    const int* src   = (const int*)d_in[1];
    const int* dst   = (const int*)d_in[2];
    const int* cu    = (const int*)d_in[3];
    const int* cv    = (const int*)d_in[4];
    const float* cf  = (const float*)d_in[5];
    const float* ws0 = (const float*)d_in[6];
    const float* wn0 = (const float*)d_in[7];
    const float* b0  = (const float*)d_in[8];
    const float* ga0 = (const float*)d_in[9];
    const float* be0 = (const float*)d_in[10];
    const float* rm0 = (const float*)d_in[11];
    const float* rv0 = (const float*)d_in[12];
    const float* ws1 = (const float*)d_in[13];
    const float* wn1 = (const float*)d_in[14];
    const float* b1  = (const float*)d_in[15];
    const float* ga1 = (const float*)d_in[16];
    const float* be1 = (const float*)d_in[17];
    const float* rm1 = (const float*)d_in[18];
    const float* rv1 = (const float*)d_in[19];
    const float* mw0 = (const float*)d_in[20];
    const float* mb0 = (const float*)d_in[21];
    const float* mw1 = (const float*)d_in[22];
    const float* mb1 = (const float*)d_in[23];
    const float* mw2 = (const float*)d_in[24];
    const float* mb2 = (const float*)d_in[25];

    int E = in_sizes[1];
    int C = in_sizes[3];
    float* y = (float*)d_out;
    float* soft = y + C;

    float *h0p, *h1p, *aggp, *pup, *pvp;
    cudaGetSymbolAddress((void**)&h0p, g_h0);
    cudaGetSymbolAddress((void**)&h1p, g_h1);
    cudaGetSymbolAddress((void**)&aggp, g_agg);
    cudaGetSymbolAddress((void**)&pup, g_pu);
    cudaGetSymbolAddress((void**)&pvp, g_pv);

    cudaFuncSetAttribute(k_gemm, cudaFuncAttributeMaxDynamicSharedMemorySize, WMMA_SMEM);
    cudaFuncSetAttribute(k_prep, cudaFuncAttributeMaxDynamicSharedMemorySize, PREP_SMEM_BYTES);
    cudaFuncSetAttribute(k_cand, cudaFuncAttributeMaxDynamicSharedMemorySize, CAND_SMEM_FLOATS * 4);

    // 1: reset barrier/lookback state
    k_zero<<<1, 256>>>();
    // 2: zero-deg + count + scan + fill (merged, 148 co-resident blocks)
    k_csr<<<NB_CSR, 1024>>>(src, dst, E);
    // 3: agg layer 0
    k_agg<<<(Nn + 7) / 8, 256>>>(x, aggp);
    // 4: gemm layer 0 — WMMA bf16-split (PROFILED SLOT)
    k_gemm<<<148, 512, WMMA_SMEM>>>(x, aggp, ws0, wn0, b0, ga0, be0, rm0, rv0, h0p, 0);
    // 5: agg layer 1
    k_agg<<<(Nn + 7) / 8, 256>>>(h0p, aggp);
    // 6: gemm layer 1 (+ nan_to_num)
    k_gemm<<<148, 512, WMMA_SMEM>>>(h0p, aggp, ws1, wn1, b1, ga1, be1, rm1, rv1, h1p, 1);
    // 7: MLP layer0 hoisted to node level (persistent)
    k_prep<<<148, 768, PREP_SMEM_BYTES>>>(h1p, mw0, pup, pvp);
    // 8: candidate tail -> y
    k_cand<<<(C + 63) / 64, 256, CAND_SMEM_FLOATS * 4>>>(pup, pvp, cu, cv, cf, mw0, mb0, mw1, mb1, mw2, mb2, y, C);
    // 9,10: softmax
    k_softA<<<128, 256>>>(y, C);
    k_softFin<<<256, 256>>>(y, soft, C);
}